// round 9
// baseline (speedup 1.0000x reference)
#include <cuda_runtime.h>
#include <cuda_fp16.h>
#include <cstdint>
#include <cstddef>

// ===================== problem constants =====================
static constexpr int NB   = 8192;               // batch
static constexpr int NIN  = 1024;               // in features
static constexpr int NOUT = 1024;               // out features
static constexpr int COEF = 8;                  // grid_size + spline_order
static constexpr int NK   = NIN + NIN * COEF;   // 9216 fused K

// ===================== gemm tiling =====================
static constexpr int BM = 128;
static constexpr int BN = 128;
static constexpr int BK = 64;                   // 64 fp16 = 128B rows in smem
static constexpr int KTILES = NK / BK;          // 144
static constexpr int STAGES = 3;

static constexpr uint32_t A_TILE = (uint32_t)BM * BK * 2;          // 16384
static constexpr uint32_t B_TILE = (uint32_t)BN * BK * 2;          // 16384
static constexpr uint32_t SMEM_TOTAL = STAGES * (A_TILE + B_TILE); // 98304 (2 CTAs/SM)

// ===================== device scratch (no allocations allowed) =====================
__device__ __align__(1024) __half g_Ah[(size_t)NB * NK];     // ~151 MB fp16 activations
__device__ __align__(1024) __half g_Wh[(size_t)NOUT * NK];   // ~19 MB fp16 packed weights

// ===================== helpers =====================
__device__ __forceinline__ uint32_t smem_u32(const void* p) {
    uint32_t a;
    asm("{ .reg .u64 t; cvta.to.shared.u64 t, %1; cvt.u32.u64 %0, t; }" : "=r"(a) : "l"(p));
    return a;
}
__device__ __forceinline__ void cp16(uint32_t dst, const void* src) {
    asm volatile("cp.async.cg.shared.global [%0], [%1], 16;" :: "r"(dst), "l"(src) : "memory");
}
#define CP_COMMIT() asm volatile("cp.async.commit_group;" ::: "memory")
#define CP_WAIT1()  asm volatile("cp.async.wait_group 1;" ::: "memory")

__device__ __forceinline__ void ldmx4(uint32_t& r0, uint32_t& r1, uint32_t& r2, uint32_t& r3,
                                      uint32_t addr) {
    asm volatile("ldmatrix.sync.aligned.m8n8.x4.shared.b16 {%0,%1,%2,%3}, [%4];"
                 : "=r"(r0), "=r"(r1), "=r"(r2), "=r"(r3) : "r"(addr));
}
__device__ __forceinline__ void mma16816(float& c0, float& c1, float& c2, float& c3,
                                         uint32_t a0, uint32_t a1, uint32_t a2, uint32_t a3,
                                         uint32_t b0, uint32_t b1) {
    asm volatile(
        "mma.sync.aligned.m16n8k16.row.col.f32.f16.f16.f32 "
        "{%0,%1,%2,%3}, {%4,%5,%6,%7}, {%8,%9}, {%0,%1,%2,%3};"
        : "+f"(c0), "+f"(c1), "+f"(c2), "+f"(c3)
        : "r"(a0), "r"(a1), "r"(a2), "r"(a3), "r"(b0), "r"(b1));
}

// ===================== kernel 1: fused prep (weight pack + activations) =====================
static constexpr int WPACK_BLOCKS = (NOUT * (NK / 2)) / 256;   // 18432
static constexpr int ACT_BLOCKS   = (NB * NIN) / 256;          // 32768

__global__ void kan_prep(const float* __restrict__ x,
                         const float* __restrict__ bw,
                         const float* __restrict__ sw) {
    if (blockIdx.x < WPACK_BLOCKS) {
        // ---- pack weights: g_Wh[o,0:1024]=bw[o,:]; g_Wh[o,1024+i*8+g]=sw[o,i,g] ----
        constexpr int HK = NK / 2;
        int p = blockIdx.x * blockDim.x + threadIdx.x;
        int o  = p / HK;
        int r  = p - o * HK;
        int kk = r * 2;
        float2 f;
        if (kk < NIN)
            f = *reinterpret_cast<const float2*>(bw + (size_t)o * NIN + kk);
        else
            f = *reinterpret_cast<const float2*>(sw + (size_t)o * (NIN * COEF) + (kk - NIN));
        reinterpret_cast<__half2*>(g_Wh + (size_t)o * NK)[r] = __floats2half2_rn(f.x, f.y);
        return;
    }
    // ---- activations: silu + closed-form uniform cubic B-spline bases ----
    int idx = (blockIdx.x - WPACK_BLOCKS) * blockDim.x + threadIdx.x;
    int b = idx >> 10;
    int i = idx & (NIN - 1);
    float v = x[idx];
    size_t ro = (size_t)b * NK;

    float s = v / (1.0f + __expf(-v));
    g_Ah[ro + i] = __float2half_rn(s);

    float xs = v * 5.0f;
    int j = (int)floorf(xs);
    j = (j < 0) ? 0 : ((j > 4) ? 4 : j);
    float t = xs - (float)j;
    float t2 = t * t, t3 = t2 * t, omt = 1.0f - t;
    float n0 = omt * omt * omt * (1.0f / 6.0f);
    float n1 = (3.0f * t3 - 6.0f * t2 + 4.0f) * (1.0f / 6.0f);
    float n2 = (-3.0f * t3 + 3.0f * t2 + 3.0f * t + 1.0f) * (1.0f / 6.0f);
    float n3 = t3 * (1.0f / 6.0f);

    __half h[8];
#pragma unroll
    for (int g = 0; g < 8; ++g) {
        float val = (g == j) ? n0 : (g == j + 1) ? n1 : (g == j + 2) ? n2
                  : (g == j + 3) ? n3 : 0.0f;
        h[g] = __float2half_rn(val);
    }
    __half2 p0 = __halves2half2(h[0], h[1]);
    __half2 p1 = __halves2half2(h[2], h[3]);
    __half2 p2 = __halves2half2(h[4], h[5]);
    __half2 p3 = __halves2half2(h[6], h[7]);
    uint4 u;
    u.x = *reinterpret_cast<uint32_t*>(&p0);
    u.y = *reinterpret_cast<uint32_t*>(&p1);
    u.z = *reinterpret_cast<uint32_t*>(&p2);
    u.w = *reinterpret_cast<uint32_t*>(&p3);
    *reinterpret_cast<uint4*>(g_Ah + ro + NIN + (size_t)i * 8) = u;
}

// ===================== kernel 2: pipelined HMMA GEMM, 2 CTAs/SM =====================
// 128x128x64 CTA tile, 64x32 warp tiles (2M x 4N), 3 smem stages.
// smem rows of 64 halves = 8 chunks of 16B, chunk swizzle phys = c ^ (row & 7).
__global__ void __launch_bounds__(256, 2) kan_gemm(float* __restrict__ out) {
    extern __shared__ __align__(1024) char smem[];
    const uint32_t sb = smem_u32(smem);
    const uint32_t sbA = sb;
    const uint32_t sbB = sb + STAGES * A_TILE;

    const int tid = threadIdx.x;
    const int lane = tid & 31;
    const int wid = tid >> 5;
    const int wm = wid & 1;          // 2 warps along M (64 rows each)
    const int wn = wid >> 1;         // 4 warps along N (32 cols each)

    const int ntile = blockIdx.x & 7;        // n fastest: A-tile L2 reuse
    const int mtile = blockIdx.x >> 3;
    const int m0 = mtile * BM;
    const int n0 = ntile * BN;

    const char* gA = (const char*)(g_Ah) + ((size_t)m0 * NK) * 2;
    const char* gB = (const char*)(g_Wh) + ((size_t)n0 * NK) * 2;

    // A: 1024 16B-chunks/stage (4/thread); B: 1024 (4/thread)
    auto load_stage = [&](int s, int kt) {
        const uint32_t dA = sbA + (uint32_t)s * A_TILE;
        const uint32_t dB = sbB + (uint32_t)s * B_TILE;
        const size_t koff = (size_t)kt * BK * 2;
#pragma unroll
        for (int i = 0; i < 4; ++i) {
            int c = tid + i * 256;
            int row = c >> 3, col = c & 7;
            uint32_t doff = ((uint32_t)(row << 3) + (uint32_t)(col ^ (row & 7))) << 4;
            size_t goff = (size_t)row * (NK * 2) + koff + (size_t)col * 16;
            cp16(dA + doff, gA + goff);
            cp16(dB + doff, gB + goff);
        }
    };

    // ---- prologue: 2 stages in flight ----
    load_stage(0, 0); CP_COMMIT();
    load_stage(1, 1); CP_COMMIT();

    // 64x32 warp tile: 4 m16 blocks x 4 n8 tiles
    float acc[4][4][4];
#pragma unroll
    for (int mi = 0; mi < 4; ++mi)
#pragma unroll
        for (int ni = 0; ni < 4; ++ni)
#pragma unroll
            for (int r = 0; r < 4; ++r) acc[mi][ni][r] = 0.0f;

    // ldmatrix lane addressing
    const int arow = wm * 64 + (lane & 15);
    const int brow = wn * 32 + (lane & 7) + ((lane >> 4) << 3);
    const uint32_t aPar  = (uint32_t)(arow & 7);
    const uint32_t bPar  = (uint32_t)(brow & 7);
    const uint32_t aKsel = (uint32_t)(lane >> 4);
    const uint32_t bKsel = (uint32_t)((lane >> 3) & 1);
    const uint32_t aBase = (uint32_t)arow << 7;   // row * 128B
    const uint32_t bBase = (uint32_t)brow << 7;

    int s = 0;          // compute stage
    int sl = 2;         // load stage
    for (int kt = 0; kt < KTILES; ++kt) {
        CP_WAIT1();                 // stage s resident
        __syncthreads();            // all warps done reading stage sl

        if (kt + 2 < KTILES) load_stage(sl, kt + 2);
        CP_COMMIT();                // empty tail groups keep accounting uniform

        const uint32_t tA = sbA + (uint32_t)s * A_TILE;
        const uint32_t tB = sbB + (uint32_t)s * B_TILE;

#pragma unroll
        for (int ks = 0; ks < 4; ++ks) {
            // A fragments: FOUR m16 blocks = full 64-row warp tile
            uint32_t a[4][4];
            const uint32_t aChunk = (((uint32_t)(ks * 2) + aKsel) ^ aPar) << 4;
#pragma unroll
            for (int mi = 0; mi < 4; ++mi)
                ldmx4(a[mi][0], a[mi][1], a[mi][2], a[mi][3],
                      tA + aBase + ((uint32_t)mi << 11) + aChunk);
            // B fragments: two 16-row groups = 4 n8 tiles (32 cols)
            uint32_t b[4][2];
            const uint32_t bChunk = (((uint32_t)(ks * 2) + bKsel) ^ bPar) << 4;
#pragma unroll
            for (int g = 0; g < 2; ++g) {
                uint32_t q0, q1, q2, q3;
                ldmx4(q0, q1, q2, q3, tB + bBase + ((uint32_t)g << 11) + bChunk);
                b[g * 2 + 0][0] = q0; b[g * 2 + 0][1] = q1;
                b[g * 2 + 1][0] = q2; b[g * 2 + 1][1] = q3;
            }
#pragma unroll
            for (int mi = 0; mi < 4; ++mi)
#pragma unroll
                for (int ni = 0; ni < 4; ++ni)
                    mma16816(acc[mi][ni][0], acc[mi][ni][1], acc[mi][ni][2], acc[mi][ni][3],
                             a[mi][0], a[mi][1], a[mi][2], a[mi][3],
                             b[ni][0], b[ni][1]);
        }

        if (++s == STAGES) s = 0;
        if (++sl == STAGES) sl = 0;
    }

    // ---- epilogue ----
    const int q = lane >> 2, p = lane & 3;
#pragma unroll
    for (int mi = 0; mi < 4; ++mi) {
        int mbase = m0 + wm * 64 + mi * 16 + q;
#pragma unroll
        for (int ni = 0; ni < 4; ++ni) {
            int nbase = n0 + wn * 32 + ni * 8 + p * 2;
            *reinterpret_cast<float2*>(out + (size_t)mbase * NOUT + nbase) =
                make_float2(acc[mi][ni][0], acc[mi][ni][1]);
            *reinterpret_cast<float2*>(out + (size_t)(mbase + 8) * NOUT + nbase) =
                make_float2(acc[mi][ni][2], acc[mi][ni][3]);
        }
    }
}

// ===================== host launcher =====================
extern "C" void kernel_launch(void* const* d_in, const int* in_sizes, int n_in,
                              void* d_out, int out_size) {
    const float* x  = (const float*)d_in[0];
    const float* bw = (const float*)d_in[1];
    const float* sw = (const float*)d_in[2];
    float* out = (float*)d_out;

    cudaFuncSetAttribute(kan_gemm, cudaFuncAttributeMaxDynamicSharedMemorySize,
                         (int)SMEM_TOTAL);

    kan_prep<<<WPACK_BLOCKS + ACT_BLOCKS, 256>>>(x, bw, sw);
    kan_gemm<<<(NB / BM) * (NOUT / BN), 256, SMEM_TOTAL>>>(out);
}

// round 10
// speedup vs baseline: 1.0580x; 1.0580x over previous
#include <cuda_runtime.h>
#include <cuda_fp16.h>
#include <cstdint>
#include <cstddef>

// ===================== problem constants =====================
static constexpr int NB   = 8192;               // batch
static constexpr int NIN  = 1024;               // in features
static constexpr int NOUT = 1024;               // out features
static constexpr int COEF = 8;                  // grid_size + spline_order
static constexpr int NK   = NIN + NIN * COEF;   // 9216 fused K

// ===================== gemm tiling =====================
static constexpr int BM = 256;
static constexpr int BN = 128;
static constexpr int BK = 128;                  // two 64-half sub-tiles per stage
static constexpr int KT_PER_TILE = NK / BK;     // 72
static constexpr int STAGES = 2;

static constexpr uint32_t A_SUB  = (uint32_t)BM * 64 * 2;      // 32768
static constexpr uint32_t B_SUB  = (uint32_t)BN * 64 * 2;      // 16384
static constexpr uint32_t A_TILE = 2 * A_SUB;                  // 65536
static constexpr uint32_t B_TILE = 2 * B_SUB;                  // 32768
static constexpr uint32_t SMEM_TOTAL = STAGES * (A_TILE + B_TILE); // 196608

// ===================== persistent split-K schedule =====================
static constexpr int NTILES  = (NB / BM) * (NOUT / BN);        // 256 output tiles
static constexpr int TOTAL_U = NTILES * KT_PER_TILE;           // 18432 (tile,kt) units
static constexpr int NCTA    = 148;                            // 1 CTA per SM
static constexpr int U_BASE  = TOTAL_U / NCTA;                 // 124
static constexpr int U_REM   = TOTAL_U % NCTA;                 // 80 CTAs get +1

// ===================== device scratch (no allocations allowed) =====================
__device__ __align__(1024) __half g_Ah[(size_t)NB * NK];       // ~151 MB fp16 activations
__device__ __align__(1024) __half g_Wh[(size_t)NOUT * NK];     // ~19 MB fp16 packed weights
__device__ __align__(1024) float  g_part[NCTA][2][BM * BN];    // ~39 MB split-tile partials

// ===================== helpers =====================
__device__ __forceinline__ uint32_t smem_u32(const void* p) {
    uint32_t a;
    asm("{ .reg .u64 t; cvta.to.shared.u64 t, %1; cvt.u32.u64 %0, t; }" : "=r"(a) : "l"(p));
    return a;
}
__device__ __forceinline__ void cp16(uint32_t dst, const void* src) {
    asm volatile("cp.async.cg.shared.global [%0], [%1], 16;" :: "r"(dst), "l"(src) : "memory");
}
#define CP_COMMIT() asm volatile("cp.async.commit_group;" ::: "memory")
#define CP_WAIT0()  asm volatile("cp.async.wait_group 0;" ::: "memory")

__device__ __forceinline__ void ldmx4(uint32_t& r0, uint32_t& r1, uint32_t& r2, uint32_t& r3,
                                      uint32_t addr) {
    asm volatile("ldmatrix.sync.aligned.m8n8.x4.shared.b16 {%0,%1,%2,%3}, [%4];"
                 : "=r"(r0), "=r"(r1), "=r"(r2), "=r"(r3) : "r"(addr));
}
__device__ __forceinline__ void mma16816(float& c0, float& c1, float& c2, float& c3,
                                         uint32_t a0, uint32_t a1, uint32_t a2, uint32_t a3,
                                         uint32_t b0, uint32_t b1) {
    asm volatile(
        "mma.sync.aligned.m16n8k16.row.col.f32.f16.f16.f32 "
        "{%0,%1,%2,%3}, {%4,%5,%6,%7}, {%8,%9}, {%0,%1,%2,%3};"
        : "+f"(c0), "+f"(c1), "+f"(c2), "+f"(c3)
        : "r"(a0), "r"(a1), "r"(a2), "r"(a3), "r"(b0), "r"(b1));
}

// ===================== kernel 1: fused prep (weight pack + activations) =====================
static constexpr int WPACK_BLOCKS = (NOUT * (NK / 2)) / 256;   // 18432
static constexpr int ACT_BLOCKS   = (NB * NIN) / 256;          // 32768

__global__ void kan_prep(const float* __restrict__ x,
                         const float* __restrict__ bw,
                         const float* __restrict__ sw) {
    if (blockIdx.x < WPACK_BLOCKS) {
        // ---- pack weights: g_Wh[o,0:1024]=bw[o,:]; g_Wh[o,1024+i*8+g]=sw[o,i,g] ----
        constexpr int HK = NK / 2;
        int p = blockIdx.x * blockDim.x + threadIdx.x;
        int o  = p / HK;
        int r  = p - o * HK;
        int kk = r * 2;
        float2 f;
        if (kk < NIN)
            f = *reinterpret_cast<const float2*>(bw + (size_t)o * NIN + kk);
        else
            f = *reinterpret_cast<const float2*>(sw + (size_t)o * (NIN * COEF) + (kk - NIN));
        reinterpret_cast<__half2*>(g_Wh + (size_t)o * NK)[r] = __floats2half2_rn(f.x, f.y);
        return;
    }
    // ---- activations: silu + closed-form uniform cubic B-spline bases ----
    int idx = (blockIdx.x - WPACK_BLOCKS) * blockDim.x + threadIdx.x;
    int b = idx >> 10;
    int i = idx & (NIN - 1);
    float v = x[idx];
    size_t ro = (size_t)b * NK;

    float s = v / (1.0f + __expf(-v));
    g_Ah[ro + i] = __float2half_rn(s);

    float xs = v * 5.0f;
    int j = (int)floorf(xs);
    j = (j < 0) ? 0 : ((j > 4) ? 4 : j);
    float t = xs - (float)j;
    float t2 = t * t, t3 = t2 * t, omt = 1.0f - t;
    float n0 = omt * omt * omt * (1.0f / 6.0f);
    float n1 = (3.0f * t3 - 6.0f * t2 + 4.0f) * (1.0f / 6.0f);
    float n2 = (-3.0f * t3 + 3.0f * t2 + 3.0f * t + 1.0f) * (1.0f / 6.0f);
    float n3 = t3 * (1.0f / 6.0f);

    __half h[8];
#pragma unroll
    for (int g = 0; g < 8; ++g) {
        float val = (g == j) ? n0 : (g == j + 1) ? n1 : (g == j + 2) ? n2
                  : (g == j + 3) ? n3 : 0.0f;
        h[g] = __float2half_rn(val);
    }
    __half2 p0 = __halves2half2(h[0], h[1]);
    __half2 p1 = __halves2half2(h[2], h[3]);
    __half2 p2 = __halves2half2(h[4], h[5]);
    __half2 p3 = __halves2half2(h[6], h[7]);
    uint4 u;
    u.x = *reinterpret_cast<uint32_t*>(&p0);
    u.y = *reinterpret_cast<uint32_t*>(&p1);
    u.z = *reinterpret_cast<uint32_t*>(&p2);
    u.w = *reinterpret_cast<uint32_t*>(&p3);
    *reinterpret_cast<uint4*>(g_Ah + ro + NIN + (size_t)i * 8) = u;
}

// ===================== kernel 2: persistent split-K HMMA GEMM =====================
// 256x128x128 CTA tile (two 64-wide sub-tiles), 64x64 warp tiles (4M x 2N),
// 2 smem stages, register double-buffered fragments. Flat (tile,kt) unit stream:
// full tiles plain-store; boundary-split tiles write partials to g_part.
__global__ void __launch_bounds__(256, 1) kan_gemm(float* __restrict__ out) {
    extern __shared__ __align__(1024) char smem[];
    const uint32_t sb = smem_u32(smem);
    const uint32_t sbA = sb;
    const uint32_t sbB = sb + STAGES * A_TILE;

    const int tid = threadIdx.x;
    const int lane = tid & 31;
    const int wid = tid >> 5;
    const int wm = wid & 3;          // 4 warps along M (64 rows each)
    const int wn = wid >> 2;         // 2 warps along N (64 cols each)

    const int c = blockIdx.x;
    const int u0 = c * U_BASE + (c < U_REM ? c : U_REM);
    const int u1 = u0 + U_BASE + (c < U_REM ? 1 : 0);

    // load-side and compute-side (tile, kt) counters
    int lt = u0 / KT_PER_TILE, lkt = u0 - lt * KT_PER_TILE;
    int ct = lt, ckt = lkt;

    // stage = [sub0 | sub1]; chunk cc: row = cc>>4, col = cc&15, sub = col>>3
    auto load_stage = [&](int s, int t, int kt) {
        const int m0 = (t >> 3) * BM;
        const int n0 = (t & 7) * BN;
        const char* gA = (const char*)(g_Ah) + ((size_t)m0 * NK) * 2;
        const char* gB = (const char*)(g_Wh) + ((size_t)n0 * NK) * 2;
        const uint32_t dA = sbA + (uint32_t)s * A_TILE;
        const uint32_t dB = sbB + (uint32_t)s * B_TILE;
        const size_t koff = (size_t)kt * BK * 2;          // 256B per K-unit
#pragma unroll
        for (int i = 0; i < 16; ++i) {                    // A: 4096 16B-chunks
            int cc = tid + i * 256;
            int row = cc >> 4, col = cc & 15;
            uint32_t doff = (uint32_t)(col >> 3) * A_SUB + ((uint32_t)row << 7)
                          + (((uint32_t)(col & 7) ^ (uint32_t)(row & 7)) << 4);
            cp16(dA + doff, gA + (size_t)row * (NK * 2) + koff + (size_t)col * 16);
        }
#pragma unroll
        for (int i = 0; i < 8; ++i) {                     // B: 2048 chunks
            int cc = tid + i * 256;
            int row = cc >> 4, col = cc & 15;
            uint32_t doff = (uint32_t)(col >> 3) * B_SUB + ((uint32_t)row << 7)
                          + (((uint32_t)(col & 7) ^ (uint32_t)(row & 7)) << 4);
            cp16(dB + doff, gB + (size_t)row * (NK * 2) + koff + (size_t)col * 16);
        }
    };

    // ---- prologue: first unit in flight ----
    load_stage(0, lt, lkt); CP_COMMIT();
    if (++lkt == KT_PER_TILE) { lkt = 0; ++lt; }

    float acc[4][8][4];
#pragma unroll
    for (int mi = 0; mi < 4; ++mi)
#pragma unroll
        for (int ni = 0; ni < 8; ++ni)
#pragma unroll
            for (int r = 0; r < 4; ++r) acc[mi][ni][r] = 0.0f;

    // ldmatrix lane addressing (within a 64-half sub-tile)
    const int arow = wm * 64 + (lane & 15);
    const int brow = wn * 64 + (lane & 7) + ((lane >> 4) << 3);
    const uint32_t aPar  = (uint32_t)(arow & 7);
    const uint32_t bPar  = (uint32_t)(brow & 7);
    const uint32_t aKsel = (uint32_t)(lane >> 4);
    const uint32_t bKsel = (uint32_t)((lane >> 3) & 1);
    const uint32_t aBase = (uint32_t)arow << 7;   // row * 128B
    const uint32_t bBase = (uint32_t)brow << 7;

    uint32_t fa[2][4][4];    // [buf][mi][reg]
    uint32_t fb[2][8][2];    // [buf][ni][reg]

    auto load_frags = [&](int buf, uint32_t tAs, uint32_t tBs, int ks) {
        const uint32_t aChunk = (((uint32_t)(ks * 2) + aKsel) ^ aPar) << 4;
#pragma unroll
        for (int mi = 0; mi < 4; ++mi)
            ldmx4(fa[buf][mi][0], fa[buf][mi][1], fa[buf][mi][2], fa[buf][mi][3],
                  tAs + aBase + ((uint32_t)mi << 11) + aChunk);
        const uint32_t bChunk = (((uint32_t)(ks * 2) + bKsel) ^ bPar) << 4;
#pragma unroll
        for (int g = 0; g < 4; ++g) {
            uint32_t q0, q1, q2, q3;
            ldmx4(q0, q1, q2, q3, tBs + bBase + ((uint32_t)g << 11) + bChunk);
            fb[buf][g * 2 + 0][0] = q0; fb[buf][g * 2 + 0][1] = q1;
            fb[buf][g * 2 + 1][0] = q2; fb[buf][g * 2 + 1][1] = q3;
        }
    };
    auto mma_block = [&](int buf) {
#pragma unroll
        for (int mi = 0; mi < 4; ++mi)
#pragma unroll
            for (int ni = 0; ni < 8; ++ni)
                mma16816(acc[mi][ni][0], acc[mi][ni][1], acc[mi][ni][2], acc[mi][ni][3],
                         fa[buf][mi][0], fa[buf][mi][1], fa[buf][mi][2], fa[buf][mi][3],
                         fb[buf][ni][0], fb[buf][ni][1]);
    };

    const int q = lane >> 2, p = lane & 3;
    // dump accumulators: full tile -> out; partial -> g_part[c][slot]
    auto dump = [&](int t, bool full) {
        if (full) {
            const int m0 = (t >> 3) * BM;
            const int n0 = (t & 7) * BN;
#pragma unroll
            for (int mi = 0; mi < 4; ++mi) {
                int mbase = m0 + wm * 64 + mi * 16 + q;
#pragma unroll
                for (int ni = 0; ni < 8; ++ni) {
                    int nbase = n0 + wn * 64 + ni * 8 + p * 2;
                    *reinterpret_cast<float2*>(out + (size_t)mbase * NOUT + nbase) =
                        make_float2(acc[mi][ni][0], acc[mi][ni][1]);
                    *reinterpret_cast<float2*>(out + (size_t)(mbase + 8) * NOUT + nbase) =
                        make_float2(acc[mi][ni][2], acc[mi][ni][3]);
                }
            }
        } else {
            const int slot = (t * KT_PER_TILE < u0) ? 0 : 1;   // head : tail
            float* pd = g_part[c][slot];
#pragma unroll
            for (int mi = 0; mi < 4; ++mi) {
                int mrel = wm * 64 + mi * 16 + q;
#pragma unroll
                for (int ni = 0; ni < 8; ++ni) {
                    int nrel = wn * 64 + ni * 8 + p * 2;
                    *reinterpret_cast<float2*>(pd + (size_t)mrel * BN + nrel) =
                        make_float2(acc[mi][ni][0], acc[mi][ni][1]);
                    *reinterpret_cast<float2*>(pd + (size_t)(mrel + 8) * BN + nrel) =
                        make_float2(acc[mi][ni][2], acc[mi][ni][3]);
                }
            }
        }
#pragma unroll
        for (int mi = 0; mi < 4; ++mi)
#pragma unroll
            for (int ni = 0; ni < 8; ++ni)
#pragma unroll
                for (int r = 0; r < 4; ++r) acc[mi][ni][r] = 0.0f;
    };

    int s = 0;
    for (int u = u0; u < u1; ++u) {
        CP_WAIT0();                 // stage s resident
        __syncthreads();            // all warps done reading stage s^1

        if (u + 1 < u1) {
            load_stage(s ^ 1, lt, lkt); CP_COMMIT();
            if (++lkt == KT_PER_TILE) { lkt = 0; ++lt; }
        }

        const uint32_t tA = sbA + (uint32_t)s * A_TILE;
        const uint32_t tB = sbB + (uint32_t)s * B_TILE;

        load_frags(0, tA, tB, 0);
#pragma unroll
        for (int k8 = 0; k8 < 8; ++k8) {      // 8 ks-steps across the two sub-tiles
            const int nk = k8 + 1;
            if (nk < 8)
                load_frags(nk & 1,
                           tA + (uint32_t)(nk >> 2) * A_SUB,
                           tB + (uint32_t)(nk >> 2) * B_SUB,
                           nk & 3);
            mma_block(k8 & 1);
        }
        s ^= 1;

        const bool tile_end  = (ckt == KT_PER_TILE - 1);
        const bool range_end = (u + 1 == u1);
        if (tile_end || range_end)
            dump(ct, tile_end && (ct * KT_PER_TILE >= u0));

        if (++ckt == KT_PER_TILE) { ckt = 0; ++ct; }
    }
}

// ===================== kernel 3: deterministic reduce of split tiles =====================
__global__ void kan_reduce(float* __restrict__ out) {
    const int c = blockIdx.x + 1;                       // boundary between CTA c-1 and c
    const int u = c * U_BASE + (c < U_REM ? c : U_REM);
    const int kt = u % KT_PER_TILE;
    if (kt == 0) return;                                // boundary on tile edge: no split
    const int t = u / KT_PER_TILE;
    const int m0 = (t >> 3) * BM;
    const int n0 = (t & 7) * BN;
    const float4* pa = reinterpret_cast<const float4*>(g_part[c - 1][1]);  // tail of c-1
    const float4* pb = reinterpret_cast<const float4*>(g_part[c][0]);      // head of c
    for (int i = threadIdx.x; i < (BM * BN) / 4; i += blockDim.x) {
        float4 va = pa[i], vb = pb[i];
        int e = i * 4;
        int r = e >> 7;            // e / BN
        int col = e & (BN - 1);
        float4 v = make_float4(va.x + vb.x, va.y + vb.y, va.z + vb.z, va.w + vb.w);
        *reinterpret_cast<float4*>(out + (size_t)(m0 + r) * NOUT + n0 + col) = v;
    }
}

// ===================== host launcher =====================
extern "C" void kernel_launch(void* const* d_in, const int* in_sizes, int n_in,
                              void* d_out, int out_size) {
    const float* x  = (const float*)d_in[0];
    const float* bw = (const float*)d_in[1];
    const float* sw = (const float*)d_in[2];
    float* out = (float*)d_out;

    cudaFuncSetAttribute(kan_gemm, cudaFuncAttributeMaxDynamicSharedMemorySize,
                         (int)SMEM_TOTAL);

    kan_prep<<<WPACK_BLOCKS + ACT_BLOCKS, 256>>>(x, bw, sw);
    kan_gemm<<<NCTA, 256, SMEM_TOTAL>>>(out);
    kan_reduce<<<NCTA - 1, 256>>>(out);
}

// round 11
// speedup vs baseline: 1.0729x; 1.0141x over previous
#include <cuda_runtime.h>
#include <cuda_fp16.h>
#include <cstdint>
#include <cstddef>

// ===================== problem constants =====================
static constexpr int NB   = 8192;               // batch
static constexpr int NIN  = 1024;               // in features
static constexpr int NOUT = 1024;               // out features
static constexpr int COEF = 8;                  // grid_size + spline_order
static constexpr int NK   = NIN + NIN * COEF;   // 9216 fused K

// ===================== gemm tiling =====================
static constexpr int BM = 256;
static constexpr int BN = 128;
static constexpr int BK = 128;                  // two 64-half sub-tiles per stage
static constexpr int KT_PER_TILE = NK / BK;     // 72
static constexpr int STAGES = 2;

static constexpr uint32_t A_SUB  = (uint32_t)BM * 64 * 2;      // 32768
static constexpr uint32_t B_SUB  = (uint32_t)BN * 64 * 2;      // 16384
static constexpr uint32_t A_TILE = 2 * A_SUB;                  // 65536
static constexpr uint32_t B_TILE = 2 * B_SUB;                  // 32768
static constexpr uint32_t SMEM_TOTAL = STAGES * (A_TILE + B_TILE); // 196608

// ===================== persistent split-K schedule =====================
static constexpr int NTILES  = (NB / BM) * (NOUT / BN);        // 256 output tiles
static constexpr int TOTAL_U = NTILES * KT_PER_TILE;           // 18432 (tile,kt) units
static constexpr int NCTA    = 148;                            // 1 CTA per SM
static constexpr int U_BASE  = TOTAL_U / NCTA;                 // 124
static constexpr int U_REM   = TOTAL_U % NCTA;                 // 80 CTAs get +1

// ===================== device scratch (no allocations allowed) =====================
__device__ __align__(1024) __half g_Ah[(size_t)NB * NK];       // ~151 MB fp16 activations
__device__ __align__(1024) __half g_Wh[(size_t)NOUT * NK];     // ~19 MB fp16 packed weights
__device__ __align__(1024) float  g_part[NCTA][2][BM * BN];    // ~39 MB split-tile partials

// ===================== helpers =====================
__device__ __forceinline__ uint32_t smem_u32(const void* p) {
    uint32_t a;
    asm("{ .reg .u64 t; cvta.to.shared.u64 t, %1; cvt.u32.u64 %0, t; }" : "=r"(a) : "l"(p));
    return a;
}
__device__ __forceinline__ void cp16(uint32_t dst, const void* src) {
    asm volatile("cp.async.cg.shared.global [%0], [%1], 16;" :: "r"(dst), "l"(src) : "memory");
}
#define CP_COMMIT() asm volatile("cp.async.commit_group;" ::: "memory")
#define CP_WAIT0()  asm volatile("cp.async.wait_group 0;" ::: "memory")

__device__ __forceinline__ void ldmx4(uint32_t& r0, uint32_t& r1, uint32_t& r2, uint32_t& r3,
                                      uint32_t addr) {
    asm volatile("ldmatrix.sync.aligned.m8n8.x4.shared.b16 {%0,%1,%2,%3}, [%4];"
                 : "=r"(r0), "=r"(r1), "=r"(r2), "=r"(r3) : "r"(addr));
}
__device__ __forceinline__ void mma16816(float& c0, float& c1, float& c2, float& c3,
                                         uint32_t a0, uint32_t a1, uint32_t a2, uint32_t a3,
                                         uint32_t b0, uint32_t b1) {
    asm volatile(
        "mma.sync.aligned.m16n8k16.row.col.f32.f16.f16.f32 "
        "{%0,%1,%2,%3}, {%4,%5,%6,%7}, {%8,%9}, {%0,%1,%2,%3};"
        : "+f"(c0), "+f"(c1), "+f"(c2), "+f"(c3)
        : "r"(a0), "r"(a1), "r"(a2), "r"(a3), "r"(b0), "r"(b1));
}

// ===================== kernel 1: prep v2 (4 elements/thread) =====================
static constexpr int WPACK_BLOCKS = (NOUT * (NK / 8)) / 256;   // 4608  (4 pairs/thread)
static constexpr int ACT_BLOCKS   = (NB * (NIN / 4)) / 256;    // 8192  (4 inputs/thread)

__global__ void kan_prep(const float* __restrict__ x,
                         const float* __restrict__ bw,
                         const float* __restrict__ sw) {
    if (blockIdx.x < WPACK_BLOCKS) {
        // ---- pack weights, 8 consecutive K-elements per thread ----
        // g_Wh[o,0:1024]=bw[o,:]; g_Wh[o,1024+i*8+g]=sw[o,i,g]
        constexpr int QK = NK / 8;                       // 1152 octets per row
        int p = blockIdx.x * blockDim.x + threadIdx.x;
        int o  = p / QK;
        int kk = (p - o * QK) * 8;                       // multiple of 8; regions align
        const float* src = (kk < NIN)
            ? bw + (size_t)o * NIN + kk
            : sw + (size_t)o * (NIN * COEF) + (kk - NIN);
        float4 f0 = *reinterpret_cast<const float4*>(src);
        float4 f1 = *reinterpret_cast<const float4*>(src + 4);
        __half2 h0 = __floats2half2_rn(f0.x, f0.y);
        __half2 h1 = __floats2half2_rn(f0.z, f0.w);
        __half2 h2 = __floats2half2_rn(f1.x, f1.y);
        __half2 h3 = __floats2half2_rn(f1.z, f1.w);
        uint4 u;
        u.x = *reinterpret_cast<uint32_t*>(&h0);
        u.y = *reinterpret_cast<uint32_t*>(&h1);
        u.z = *reinterpret_cast<uint32_t*>(&h2);
        u.w = *reinterpret_cast<uint32_t*>(&h3);
        *reinterpret_cast<uint4*>(g_Wh + (size_t)o * NK + kk) = u;
        return;
    }
    // ---- activations: 4 consecutive inputs per thread ----
    int idx = (blockIdx.x - WPACK_BLOCKS) * blockDim.x + threadIdx.x;
    int b  = idx >> 8;                    // / (NIN/4)
    int i0 = (idx & 255) << 2;            // 4-aligned input index
    const float4 v4 = *reinterpret_cast<const float4*>(x + (size_t)b * NIN + i0);
    const float vv[4] = {v4.x, v4.y, v4.z, v4.w};
    const size_t ro = (size_t)b * NK;

    // silu: 4 halves = one 8B store
    __half2 s01 = __floats2half2_rn(vv[0] / (1.0f + __expf(-vv[0])),
                                    vv[1] / (1.0f + __expf(-vv[1])));
    __half2 s23 = __floats2half2_rn(vv[2] / (1.0f + __expf(-vv[2])),
                                    vv[3] / (1.0f + __expf(-vv[3])));
    uint2 su;
    su.x = *reinterpret_cast<uint32_t*>(&s01);
    su.y = *reinterpret_cast<uint32_t*>(&s23);
    *reinterpret_cast<uint2*>(g_Ah + ro + i0) = su;

    // uniform cubic B-spline bases: one 16B store per input
    __half* base_dst = g_Ah + ro + NIN + (size_t)i0 * 8;
#pragma unroll
    for (int e = 0; e < 4; ++e) {
        float v = vv[e];
        float xs = v * 5.0f;
        int j = (int)floorf(xs);
        j = (j < 0) ? 0 : ((j > 4) ? 4 : j);
        float t = xs - (float)j;
        float t2 = t * t, t3 = t2 * t, omt = 1.0f - t;
        float n0 = omt * omt * omt * (1.0f / 6.0f);
        float n1 = (3.0f * t3 - 6.0f * t2 + 4.0f) * (1.0f / 6.0f);
        float n2 = (-3.0f * t3 + 3.0f * t2 + 3.0f * t + 1.0f) * (1.0f / 6.0f);
        float n3 = t3 * (1.0f / 6.0f);

        __half h[8];
#pragma unroll
        for (int g = 0; g < 8; ++g) {
            float val = (g == j) ? n0 : (g == j + 1) ? n1 : (g == j + 2) ? n2
                      : (g == j + 3) ? n3 : 0.0f;
            h[g] = __float2half_rn(val);
        }
        __half2 p0 = __halves2half2(h[0], h[1]);
        __half2 p1 = __halves2half2(h[2], h[3]);
        __half2 p2 = __halves2half2(h[4], h[5]);
        __half2 p3 = __halves2half2(h[6], h[7]);
        uint4 u;
        u.x = *reinterpret_cast<uint32_t*>(&p0);
        u.y = *reinterpret_cast<uint32_t*>(&p1);
        u.z = *reinterpret_cast<uint32_t*>(&p2);
        u.w = *reinterpret_cast<uint32_t*>(&p3);
        *reinterpret_cast<uint4*>(base_dst + (size_t)e * 8) = u;
    }
}

// ===================== kernel 2: persistent split-K HMMA GEMM (unchanged from R10) =====
__global__ void __launch_bounds__(256, 1) kan_gemm(float* __restrict__ out) {
    extern __shared__ __align__(1024) char smem[];
    const uint32_t sb = smem_u32(smem);
    const uint32_t sbA = sb;
    const uint32_t sbB = sb + STAGES * A_TILE;

    const int tid = threadIdx.x;
    const int lane = tid & 31;
    const int wid = tid >> 5;
    const int wm = wid & 3;          // 4 warps along M (64 rows each)
    const int wn = wid >> 2;         // 2 warps along N (64 cols each)

    const int c = blockIdx.x;
    const int u0 = c * U_BASE + (c < U_REM ? c : U_REM);
    const int u1 = u0 + U_BASE + (c < U_REM ? 1 : 0);

    int lt = u0 / KT_PER_TILE, lkt = u0 - lt * KT_PER_TILE;
    int ct = lt, ckt = lkt;

    auto load_stage = [&](int s, int t, int kt) {
        const int m0 = (t >> 3) * BM;
        const int n0 = (t & 7) * BN;
        const char* gA = (const char*)(g_Ah) + ((size_t)m0 * NK) * 2;
        const char* gB = (const char*)(g_Wh) + ((size_t)n0 * NK) * 2;
        const uint32_t dA = sbA + (uint32_t)s * A_TILE;
        const uint32_t dB = sbB + (uint32_t)s * B_TILE;
        const size_t koff = (size_t)kt * BK * 2;
#pragma unroll
        for (int i = 0; i < 16; ++i) {
            int cc = tid + i * 256;
            int row = cc >> 4, col = cc & 15;
            uint32_t doff = (uint32_t)(col >> 3) * A_SUB + ((uint32_t)row << 7)
                          + (((uint32_t)(col & 7) ^ (uint32_t)(row & 7)) << 4);
            cp16(dA + doff, gA + (size_t)row * (NK * 2) + koff + (size_t)col * 16);
        }
#pragma unroll
        for (int i = 0; i < 8; ++i) {
            int cc = tid + i * 256;
            int row = cc >> 4, col = cc & 15;
            uint32_t doff = (uint32_t)(col >> 3) * B_SUB + ((uint32_t)row << 7)
                          + (((uint32_t)(col & 7) ^ (uint32_t)(row & 7)) << 4);
            cp16(dB + doff, gB + (size_t)row * (NK * 2) + koff + (size_t)col * 16);
        }
    };

    load_stage(0, lt, lkt); CP_COMMIT();
    if (++lkt == KT_PER_TILE) { lkt = 0; ++lt; }

    float acc[4][8][4];
#pragma unroll
    for (int mi = 0; mi < 4; ++mi)
#pragma unroll
        for (int ni = 0; ni < 8; ++ni)
#pragma unroll
            for (int r = 0; r < 4; ++r) acc[mi][ni][r] = 0.0f;

    const int arow = wm * 64 + (lane & 15);
    const int brow = wn * 64 + (lane & 7) + ((lane >> 4) << 3);
    const uint32_t aPar  = (uint32_t)(arow & 7);
    const uint32_t bPar  = (uint32_t)(brow & 7);
    const uint32_t aKsel = (uint32_t)(lane >> 4);
    const uint32_t bKsel = (uint32_t)((lane >> 3) & 1);
    const uint32_t aBase = (uint32_t)arow << 7;
    const uint32_t bBase = (uint32_t)brow << 7;

    uint32_t fa[2][4][4];
    uint32_t fb[2][8][2];

    auto load_frags = [&](int buf, uint32_t tAs, uint32_t tBs, int ks) {
        const uint32_t aChunk = (((uint32_t)(ks * 2) + aKsel) ^ aPar) << 4;
#pragma unroll
        for (int mi = 0; mi < 4; ++mi)
            ldmx4(fa[buf][mi][0], fa[buf][mi][1], fa[buf][mi][2], fa[buf][mi][3],
                  tAs + aBase + ((uint32_t)mi << 11) + aChunk);
        const uint32_t bChunk = (((uint32_t)(ks * 2) + bKsel) ^ bPar) << 4;
#pragma unroll
        for (int g = 0; g < 4; ++g) {
            uint32_t q0, q1, q2, q3;
            ldmx4(q0, q1, q2, q3, tBs + bBase + ((uint32_t)g << 11) + bChunk);
            fb[buf][g * 2 + 0][0] = q0; fb[buf][g * 2 + 0][1] = q1;
            fb[buf][g * 2 + 1][0] = q2; fb[buf][g * 2 + 1][1] = q3;
        }
    };
    auto mma_block = [&](int buf) {
#pragma unroll
        for (int mi = 0; mi < 4; ++mi)
#pragma unroll
            for (int ni = 0; ni < 8; ++ni)
                mma16816(acc[mi][ni][0], acc[mi][ni][1], acc[mi][ni][2], acc[mi][ni][3],
                         fa[buf][mi][0], fa[buf][mi][1], fa[buf][mi][2], fa[buf][mi][3],
                         fb[buf][ni][0], fb[buf][ni][1]);
    };

    const int q = lane >> 2, p = lane & 3;
    auto dump = [&](int t, bool full) {
        if (full) {
            const int m0 = (t >> 3) * BM;
            const int n0 = (t & 7) * BN;
#pragma unroll
            for (int mi = 0; mi < 4; ++mi) {
                int mbase = m0 + wm * 64 + mi * 16 + q;
#pragma unroll
                for (int ni = 0; ni < 8; ++ni) {
                    int nbase = n0 + wn * 64 + ni * 8 + p * 2;
                    *reinterpret_cast<float2*>(out + (size_t)mbase * NOUT + nbase) =
                        make_float2(acc[mi][ni][0], acc[mi][ni][1]);
                    *reinterpret_cast<float2*>(out + (size_t)(mbase + 8) * NOUT + nbase) =
                        make_float2(acc[mi][ni][2], acc[mi][ni][3]);
                }
            }
        } else {
            const int slot = (t * KT_PER_TILE < u0) ? 0 : 1;   // head : tail
            float* pd = g_part[c][slot];
#pragma unroll
            for (int mi = 0; mi < 4; ++mi) {
                int mrel = wm * 64 + mi * 16 + q;
#pragma unroll
                for (int ni = 0; ni < 8; ++ni) {
                    int nrel = wn * 64 + ni * 8 + p * 2;
                    *reinterpret_cast<float2*>(pd + (size_t)mrel * BN + nrel) =
                        make_float2(acc[mi][ni][0], acc[mi][ni][1]);
                    *reinterpret_cast<float2*>(pd + (size_t)(mrel + 8) * BN + nrel) =
                        make_float2(acc[mi][ni][2], acc[mi][ni][3]);
                }
            }
        }
#pragma unroll
        for (int mi = 0; mi < 4; ++mi)
#pragma unroll
            for (int ni = 0; ni < 8; ++ni)
#pragma unroll
                for (int r = 0; r < 4; ++r) acc[mi][ni][r] = 0.0f;
    };

    int s = 0;
    for (int u = u0; u < u1; ++u) {
        CP_WAIT0();
        __syncthreads();

        if (u + 1 < u1) {
            load_stage(s ^ 1, lt, lkt); CP_COMMIT();
            if (++lkt == KT_PER_TILE) { lkt = 0; ++lt; }
        }

        const uint32_t tA = sbA + (uint32_t)s * A_TILE;
        const uint32_t tB = sbB + (uint32_t)s * B_TILE;

        load_frags(0, tA, tB, 0);
#pragma unroll
        for (int k8 = 0; k8 < 8; ++k8) {
            const int nk = k8 + 1;
            if (nk < 8)
                load_frags(nk & 1,
                           tA + (uint32_t)(nk >> 2) * A_SUB,
                           tB + (uint32_t)(nk >> 2) * B_SUB,
                           nk & 3);
            mma_block(k8 & 1);
        }
        s ^= 1;

        const bool tile_end  = (ckt == KT_PER_TILE - 1);
        const bool range_end = (u + 1 == u1);
        if (tile_end || range_end)
            dump(ct, tile_end && (ct * KT_PER_TILE >= u0));

        if (++ckt == KT_PER_TILE) { ckt = 0; ++ct; }
    }
}

// ===================== kernel 3: deterministic reduce of split tiles (unchanged) =======
__global__ void kan_reduce(float* __restrict__ out) {
    const int c = blockIdx.x + 1;
    const int u = c * U_BASE + (c < U_REM ? c : U_REM);
    const int kt = u % KT_PER_TILE;
    if (kt == 0) return;
    const int t = u / KT_PER_TILE;
    const int m0 = (t >> 3) * BM;
    const int n0 = (t & 7) * BN;
    const float4* pa = reinterpret_cast<const float4*>(g_part[c - 1][1]);
    const float4* pb = reinterpret_cast<const float4*>(g_part[c][0]);
    for (int i = threadIdx.x; i < (BM * BN) / 4; i += blockDim.x) {
        float4 va = pa[i], vb = pb[i];
        int e = i * 4;
        int r = e >> 7;
        int col = e & (BN - 1);
        float4 v = make_float4(va.x + vb.x, va.y + vb.y, va.z + vb.z, va.w + vb.w);
        *reinterpret_cast<float4*>(out + (size_t)(m0 + r) * NOUT + n0 + col) = v;
    }
}

// ===================== host launcher =====================
extern "C" void kernel_launch(void* const* d_in, const int* in_sizes, int n_in,
                              void* d_out, int out_size) {
    const float* x  = (const float*)d_in[0];
    const float* bw = (const float*)d_in[1];
    const float* sw = (const float*)d_in[2];
    float* out = (float*)d_out;

    cudaFuncSetAttribute(kan_gemm, cudaFuncAttributeMaxDynamicSharedMemorySize,
                         (int)SMEM_TOTAL);

    kan_prep<<<WPACK_BLOCKS + ACT_BLOCKS, 256>>>(x, bw, sw);
    kan_gemm<<<NCTA, 256, SMEM_TOTAL>>>(out);
    kan_reduce<<<NCTA - 1, 256>>>(out);
}

// round 12
// speedup vs baseline: 1.0821x; 1.0085x over previous
#include <cuda_runtime.h>
#include <cuda_fp16.h>
#include <cstdint>
#include <cstddef>

// ===================== problem constants =====================
static constexpr int NB   = 8192;               // batch
static constexpr int NIN  = 1024;               // in features
static constexpr int NOUT = 1024;               // out features
static constexpr int COEF = 8;                  // grid_size + spline_order
static constexpr int NK   = NIN + NIN * COEF;   // 9216 fused K

// ===================== gemm tiling =====================
static constexpr int BM = 256;
static constexpr int BN = 128;
static constexpr int BK = 128;                  // two 64-half sub-tiles per stage
static constexpr int KT_PER_TILE = NK / BK;     // 72
static constexpr int STAGES = 2;

static constexpr uint32_t A_SUB  = (uint32_t)BM * 64 * 2;      // 32768
static constexpr uint32_t B_SUB  = (uint32_t)BN * 64 * 2;      // 16384
static constexpr uint32_t A_TILE = 2 * A_SUB;                  // 65536
static constexpr uint32_t B_TILE = 2 * B_SUB;                  // 32768
static constexpr uint32_t SMEM_TOTAL = STAGES * (A_TILE + B_TILE); // 196608

// ===================== persistent split-K schedule =====================
static constexpr int NTILES  = (NB / BM) * (NOUT / BN);        // 256 output tiles
static constexpr int TOTAL_U = NTILES * KT_PER_TILE;           // 18432 (tile,kt) units
static constexpr int NCTA    = 148;                            // 1 CTA per SM
static constexpr int U_BASE  = TOTAL_U / NCTA;                 // 124
static constexpr int U_REM   = TOTAL_U % NCTA;                 // 80 CTAs get +1

// ===================== device scratch (no allocations allowed) =====================
__device__ __align__(1024) __half g_Ah[(size_t)NB * NK];       // ~151 MB fp16 activations
__device__ __align__(1024) __half g_Wh[(size_t)NOUT * NK];     // ~19 MB fp16 packed weights
__device__ __align__(1024) float  g_part[NCTA][2][BM * BN];    // ~39 MB split-tile partials

// ===================== helpers =====================
__device__ __forceinline__ uint32_t smem_u32(const void* p) {
    uint32_t a;
    asm("{ .reg .u64 t; cvta.to.shared.u64 t, %1; cvt.u32.u64 %0, t; }" : "=r"(a) : "l"(p));
    return a;
}
__device__ __forceinline__ void cp16(uint32_t dst, const void* src) {
    asm volatile("cp.async.cg.shared.global [%0], [%1], 16;" :: "r"(dst), "l"(src) : "memory");
}
#define CP_COMMIT() asm volatile("cp.async.commit_group;" ::: "memory")
#define CP_WAIT0()  asm volatile("cp.async.wait_group 0;" ::: "memory")

__device__ __forceinline__ void ldmx4(uint32_t& r0, uint32_t& r1, uint32_t& r2, uint32_t& r3,
                                      uint32_t addr) {
    asm volatile("ldmatrix.sync.aligned.m8n8.x4.shared.b16 {%0,%1,%2,%3}, [%4];"
                 : "=r"(r0), "=r"(r1), "=r"(r2), "=r"(r3) : "r"(addr));
}
__device__ __forceinline__ void mma16816(float& c0, float& c1, float& c2, float& c3,
                                         uint32_t a0, uint32_t a1, uint32_t a2, uint32_t a3,
                                         uint32_t b0, uint32_t b1) {
    asm volatile(
        "mma.sync.aligned.m16n8k16.row.col.f32.f16.f16.f32 "
        "{%0,%1,%2,%3}, {%4,%5,%6,%7}, {%8,%9}, {%0,%1,%2,%3};"
        : "+f"(c0), "+f"(c1), "+f"(c2), "+f"(c3)
        : "r"(a0), "r"(a1), "r"(a2), "r"(a3), "r"(b0), "r"(b1));
}

// ===================== kernel 1: prep v3 (branchless spline packing) =====================
static constexpr int WPACK_BLOCKS = (NOUT * (NK / 8)) / 256;   // 4608  (4 pairs/thread)
static constexpr int ACT_BLOCKS   = (NB * (NIN / 4)) / 256;    // 8192  (4 inputs/thread)

__global__ void kan_prep(const float* __restrict__ x,
                         const float* __restrict__ bw,
                         const float* __restrict__ sw) {
    if (blockIdx.x < WPACK_BLOCKS) {
        // ---- pack weights, 8 consecutive K-elements per thread ----
        // g_Wh[o,0:1024]=bw[o,:]; g_Wh[o,1024+i*8+g]=sw[o,i,g]
        constexpr int QK = NK / 8;                       // 1152 octets per row
        int p = blockIdx.x * blockDim.x + threadIdx.x;
        int o  = p / QK;
        int kk = (p - o * QK) * 8;                       // multiple of 8; regions align
        const float* src = (kk < NIN)
            ? bw + (size_t)o * NIN + kk
            : sw + (size_t)o * (NIN * COEF) + (kk - NIN);
        float4 f0 = *reinterpret_cast<const float4*>(src);
        float4 f1 = *reinterpret_cast<const float4*>(src + 4);
        __half2 h0 = __floats2half2_rn(f0.x, f0.y);
        __half2 h1 = __floats2half2_rn(f0.z, f0.w);
        __half2 h2 = __floats2half2_rn(f1.x, f1.y);
        __half2 h3 = __floats2half2_rn(f1.z, f1.w);
        uint4 u;
        u.x = *reinterpret_cast<uint32_t*>(&h0);
        u.y = *reinterpret_cast<uint32_t*>(&h1);
        u.z = *reinterpret_cast<uint32_t*>(&h2);
        u.w = *reinterpret_cast<uint32_t*>(&h3);
        *reinterpret_cast<uint4*>(g_Wh + (size_t)o * NK + kk) = u;
        return;
    }
    // ---- activations: 4 consecutive inputs per thread ----
    int idx = (blockIdx.x - WPACK_BLOCKS) * blockDim.x + threadIdx.x;
    int b  = idx >> 8;                    // / (NIN/4)
    int i0 = (idx & 255) << 2;            // 4-aligned input index
    const float4 v4 = *reinterpret_cast<const float4*>(x + (size_t)b * NIN + i0);
    const float vv[4] = {v4.x, v4.y, v4.z, v4.w};
    const size_t ro = (size_t)b * NK;

    // silu: 4 halves = one 8B store
    __half2 s01 = __floats2half2_rn(vv[0] / (1.0f + __expf(-vv[0])),
                                    vv[1] / (1.0f + __expf(-vv[1])));
    __half2 s23 = __floats2half2_rn(vv[2] / (1.0f + __expf(-vv[2])),
                                    vv[3] / (1.0f + __expf(-vv[3])));
    uint2 su;
    su.x = *reinterpret_cast<uint32_t*>(&s01);
    su.y = *reinterpret_cast<uint32_t*>(&s23);
    *reinterpret_cast<uint2*>(g_Ah + ro + i0) = su;

    // uniform cubic B-spline bases: 4 nonzero values at slots j..j+3 of 8.
    // Pack (n0..n3) into 64-bit P and shift left by 16*j within a 128-bit lane.
    __half* base_dst = g_Ah + ro + NIN + (size_t)i0 * 8;
#pragma unroll
    for (int e = 0; e < 4; ++e) {
        float v = vv[e];
        float xs = v * 5.0f;
        int j = __float2int_rd(xs);       // x in [0,1) -> j in [0,4]
        j = (j > 4) ? 4 : ((j < 0) ? 0 : j);
        float t = xs - (float)j;
        float t2 = t * t, omt = 1.0f - t;
        // Horner forms of the uniform cubic B-spline basis values
        float n0 = omt * omt * omt * (1.0f / 6.0f);
        float n1 = (0.5f * t - 1.0f) * t2 + (2.0f / 3.0f);
        float n2 = ((-0.5f * t + 0.5f) * t + 0.5f) * t + (1.0f / 6.0f);
        float n3 = t * t2 * (1.0f / 6.0f);

        __half2 q01 = __floats2half2_rn(n0, n1);
        __half2 q23 = __floats2half2_rn(n2, n3);
        uint64_t P = (uint64_t)(*reinterpret_cast<uint32_t*>(&q01))
                   | ((uint64_t)(*reinterpret_cast<uint32_t*>(&q23)) << 32);
        const int sh = j * 16;
        uint64_t lo, hi;
        if (j == 0)      { lo = P;        hi = 0; }
        else if (j < 4)  { lo = P << sh;  hi = P >> (64 - sh); }
        else             { lo = 0;        hi = P; }
        uint4 u;
        u.x = (uint32_t)lo;  u.y = (uint32_t)(lo >> 32);
        u.z = (uint32_t)hi;  u.w = (uint32_t)(hi >> 32);
        *reinterpret_cast<uint4*>(base_dst + (size_t)e * 8) = u;
    }
}

// ===================== kernel 2: persistent split-K HMMA GEMM (unchanged from R10) =====
__global__ void __launch_bounds__(256, 1) kan_gemm(float* __restrict__ out) {
    extern __shared__ __align__(1024) char smem[];
    const uint32_t sb = smem_u32(smem);
    const uint32_t sbA = sb;
    const uint32_t sbB = sb + STAGES * A_TILE;

    const int tid = threadIdx.x;
    const int lane = tid & 31;
    const int wid = tid >> 5;
    const int wm = wid & 3;          // 4 warps along M (64 rows each)
    const int wn = wid >> 2;         // 2 warps along N (64 cols each)

    const int c = blockIdx.x;
    const int u0 = c * U_BASE + (c < U_REM ? c : U_REM);
    const int u1 = u0 + U_BASE + (c < U_REM ? 1 : 0);

    int lt = u0 / KT_PER_TILE, lkt = u0 - lt * KT_PER_TILE;
    int ct = lt, ckt = lkt;

    auto load_stage = [&](int s, int t, int kt) {
        const int m0 = (t >> 3) * BM;
        const int n0 = (t & 7) * BN;
        const char* gA = (const char*)(g_Ah) + ((size_t)m0 * NK) * 2;
        const char* gB = (const char*)(g_Wh) + ((size_t)n0 * NK) * 2;
        const uint32_t dA = sbA + (uint32_t)s * A_TILE;
        const uint32_t dB = sbB + (uint32_t)s * B_TILE;
        const size_t koff = (size_t)kt * BK * 2;
#pragma unroll
        for (int i = 0; i < 16; ++i) {
            int cc = tid + i * 256;
            int row = cc >> 4, col = cc & 15;
            uint32_t doff = (uint32_t)(col >> 3) * A_SUB + ((uint32_t)row << 7)
                          + (((uint32_t)(col & 7) ^ (uint32_t)(row & 7)) << 4);
            cp16(dA + doff, gA + (size_t)row * (NK * 2) + koff + (size_t)col * 16);
        }
#pragma unroll
        for (int i = 0; i < 8; ++i) {
            int cc = tid + i * 256;
            int row = cc >> 4, col = cc & 15;
            uint32_t doff = (uint32_t)(col >> 3) * B_SUB + ((uint32_t)row << 7)
                          + (((uint32_t)(col & 7) ^ (uint32_t)(row & 7)) << 4);
            cp16(dB + doff, gB + (size_t)row * (NK * 2) + koff + (size_t)col * 16);
        }
    };

    load_stage(0, lt, lkt); CP_COMMIT();
    if (++lkt == KT_PER_TILE) { lkt = 0; ++lt; }

    float acc[4][8][4];
#pragma unroll
    for (int mi = 0; mi < 4; ++mi)
#pragma unroll
        for (int ni = 0; ni < 8; ++ni)
#pragma unroll
            for (int r = 0; r < 4; ++r) acc[mi][ni][r] = 0.0f;

    const int arow = wm * 64 + (lane & 15);
    const int brow = wn * 64 + (lane & 7) + ((lane >> 4) << 3);
    const uint32_t aPar  = (uint32_t)(arow & 7);
    const uint32_t bPar  = (uint32_t)(brow & 7);
    const uint32_t aKsel = (uint32_t)(lane >> 4);
    const uint32_t bKsel = (uint32_t)((lane >> 3) & 1);
    const uint32_t aBase = (uint32_t)arow << 7;
    const uint32_t bBase = (uint32_t)brow << 7;

    uint32_t fa[2][4][4];
    uint32_t fb[2][8][2];

    auto load_frags = [&](int buf, uint32_t tAs, uint32_t tBs, int ks) {
        const uint32_t aChunk = (((uint32_t)(ks * 2) + aKsel) ^ aPar) << 4;
#pragma unroll
        for (int mi = 0; mi < 4; ++mi)
            ldmx4(fa[buf][mi][0], fa[buf][mi][1], fa[buf][mi][2], fa[buf][mi][3],
                  tAs + aBase + ((uint32_t)mi << 11) + aChunk);
        const uint32_t bChunk = (((uint32_t)(ks * 2) + bKsel) ^ bPar) << 4;
#pragma unroll
        for (int g = 0; g < 4; ++g) {
            uint32_t q0, q1, q2, q3;
            ldmx4(q0, q1, q2, q3, tBs + bBase + ((uint32_t)g << 11) + bChunk);
            fb[buf][g * 2 + 0][0] = q0; fb[buf][g * 2 + 0][1] = q1;
            fb[buf][g * 2 + 1][0] = q2; fb[buf][g * 2 + 1][1] = q3;
        }
    };
    auto mma_block = [&](int buf) {
#pragma unroll
        for (int mi = 0; mi < 4; ++mi)
#pragma unroll
            for (int ni = 0; ni < 8; ++ni)
                mma16816(acc[mi][ni][0], acc[mi][ni][1], acc[mi][ni][2], acc[mi][ni][3],
                         fa[buf][mi][0], fa[buf][mi][1], fa[buf][mi][2], fa[buf][mi][3],
                         fb[buf][ni][0], fb[buf][ni][1]);
    };

    const int q = lane >> 2, p = lane & 3;
    auto dump = [&](int t, bool full) {
        if (full) {
            const int m0 = (t >> 3) * BM;
            const int n0 = (t & 7) * BN;
#pragma unroll
            for (int mi = 0; mi < 4; ++mi) {
                int mbase = m0 + wm * 64 + mi * 16 + q;
#pragma unroll
                for (int ni = 0; ni < 8; ++ni) {
                    int nbase = n0 + wn * 64 + ni * 8 + p * 2;
                    *reinterpret_cast<float2*>(out + (size_t)mbase * NOUT + nbase) =
                        make_float2(acc[mi][ni][0], acc[mi][ni][1]);
                    *reinterpret_cast<float2*>(out + (size_t)(mbase + 8) * NOUT + nbase) =
                        make_float2(acc[mi][ni][2], acc[mi][ni][3]);
                }
            }
        } else {
            const int slot = (t * KT_PER_TILE < u0) ? 0 : 1;   // head : tail
            float* pd = g_part[c][slot];
#pragma unroll
            for (int mi = 0; mi < 4; ++mi) {
                int mrel = wm * 64 + mi * 16 + q;
#pragma unroll
                for (int ni = 0; ni < 8; ++ni) {
                    int nrel = wn * 64 + ni * 8 + p * 2;
                    *reinterpret_cast<float2*>(pd + (size_t)mrel * BN + nrel) =
                        make_float2(acc[mi][ni][0], acc[mi][ni][1]);
                    *reinterpret_cast<float2*>(pd + (size_t)(mrel + 8) * BN + nrel) =
                        make_float2(acc[mi][ni][2], acc[mi][ni][3]);
                }
            }
        }
#pragma unroll
        for (int mi = 0; mi < 4; ++mi)
#pragma unroll
            for (int ni = 0; ni < 8; ++ni)
#pragma unroll
                for (int r = 0; r < 4; ++r) acc[mi][ni][r] = 0.0f;
    };

    int s = 0;
    for (int u = u0; u < u1; ++u) {
        CP_WAIT0();
        __syncthreads();

        if (u + 1 < u1) {
            load_stage(s ^ 1, lt, lkt); CP_COMMIT();
            if (++lkt == KT_PER_TILE) { lkt = 0; ++lt; }
        }

        const uint32_t tA = sbA + (uint32_t)s * A_TILE;
        const uint32_t tB = sbB + (uint32_t)s * B_TILE;

        load_frags(0, tA, tB, 0);
#pragma unroll
        for (int k8 = 0; k8 < 8; ++k8) {
            const int nk = k8 + 1;
            if (nk < 8)
                load_frags(nk & 1,
                           tA + (uint32_t)(nk >> 2) * A_SUB,
                           tB + (uint32_t)(nk >> 2) * B_SUB,
                           nk & 3);
            mma_block(k8 & 1);
        }
        s ^= 1;

        const bool tile_end  = (ckt == KT_PER_TILE - 1);
        const bool range_end = (u + 1 == u1);
        if (tile_end || range_end)
            dump(ct, tile_end && (ct * KT_PER_TILE >= u0));

        if (++ckt == KT_PER_TILE) { ckt = 0; ++ct; }
    }
}

// ===================== kernel 3: deterministic reduce of split tiles (unchanged) =======
__global__ void kan_reduce(float* __restrict__ out) {
    const int c = blockIdx.x + 1;
    const int u = c * U_BASE + (c < U_REM ? c : U_REM);
    const int kt = u % KT_PER_TILE;
    if (kt == 0) return;
    const int t = u / KT_PER_TILE;
    const int m0 = (t >> 3) * BM;
    const int n0 = (t & 7) * BN;
    const float4* pa = reinterpret_cast<const float4*>(g_part[c - 1][1]);
    const float4* pb = reinterpret_cast<const float4*>(g_part[c][0]);
    for (int i = threadIdx.x; i < (BM * BN) / 4; i += blockDim.x) {
        float4 va = pa[i], vb = pb[i];
        int e = i * 4;
        int r = e >> 7;
        int col = e & (BN - 1);
        float4 v = make_float4(va.x + vb.x, va.y + vb.y, va.z + vb.z, va.w + vb.w);
        *reinterpret_cast<float4*>(out + (size_t)(m0 + r) * NOUT + n0 + col) = v;
    }
}

// ===================== host launcher =====================
extern "C" void kernel_launch(void* const* d_in, const int* in_sizes, int n_in,
                              void* d_out, int out_size) {
    const float* x  = (const float*)d_in[0];
    const float* bw = (const float*)d_in[1];
    const float* sw = (const float*)d_in[2];
    float* out = (float*)d_out;

    cudaFuncSetAttribute(kan_gemm, cudaFuncAttributeMaxDynamicSharedMemorySize,
                         (int)SMEM_TOTAL);

    kan_prep<<<WPACK_BLOCKS + ACT_BLOCKS, 256>>>(x, bw, sw);
    kan_gemm<<<NCTA, 256, SMEM_TOTAL>>>(out);
    kan_reduce<<<NCTA - 1, 256>>>(out);
}

// round 13
// speedup vs baseline: 1.0896x; 1.0070x over previous
#include <cuda_runtime.h>
#include <cuda_fp16.h>
#include <cstdint>
#include <cstddef>

// ===================== problem constants =====================
static constexpr int NB   = 8192;               // batch
static constexpr int NIN  = 1024;               // in features
static constexpr int NOUT = 1024;               // out features
static constexpr int COEF = 8;                  // grid_size + spline_order
static constexpr int NK   = NIN + NIN * COEF;   // 9216 fused K

// ===================== gemm tiling =====================
static constexpr int BM = 256;
static constexpr int BN = 128;
static constexpr int BK = 128;                  // two 64-half sub-tiles per stage
static constexpr int KT_PER_TILE = NK / BK;     // 72
static constexpr int STAGES = 2;

static constexpr uint32_t A_SUB  = (uint32_t)BM * 64 * 2;      // 32768
static constexpr uint32_t B_SUB  = (uint32_t)BN * 64 * 2;      // 16384
static constexpr uint32_t A_TILE = 2 * A_SUB;                  // 65536
static constexpr uint32_t B_TILE = 2 * B_SUB;                  // 32768
static constexpr uint32_t SMEM_TOTAL = STAGES * (A_TILE + B_TILE); // 196608

// ===================== persistent split-K schedule =====================
static constexpr int NTILES  = (NB / BM) * (NOUT / BN);        // 256 output tiles
static constexpr int TOTAL_U = NTILES * KT_PER_TILE;           // 18432 (tile,kt) units
static constexpr int NCTA    = 148;                            // 1 CTA per SM
static constexpr int U_BASE  = TOTAL_U / NCTA;                 // 124
static constexpr int U_REM   = TOTAL_U % NCTA;                 // 80 CTAs get +1

// ===================== device scratch (no allocations allowed) =====================
__device__ __align__(1024) __half g_Ah[(size_t)NB * NK];       // ~151 MB fp16 activations
__device__ __align__(1024) __half g_Wh[(size_t)NOUT * NK];     // ~19 MB fp16 packed weights
__device__ __align__(1024) float  g_part[NCTA][2][BM * BN];    // ~39 MB split-tile partials

// ===================== helpers =====================
__device__ __forceinline__ uint32_t smem_u32(const void* p) {
    uint32_t a;
    asm("{ .reg .u64 t; cvta.to.shared.u64 t, %1; cvt.u32.u64 %0, t; }" : "=r"(a) : "l"(p));
    return a;
}
__device__ __forceinline__ void cp16(uint32_t dst, const void* src) {
    asm volatile("cp.async.cg.shared.global [%0], [%1], 16;" :: "r"(dst), "l"(src) : "memory");
}
#define CP_COMMIT() asm volatile("cp.async.commit_group;" ::: "memory")
#define CP_WAIT0()  asm volatile("cp.async.wait_group 0;" ::: "memory")

__device__ __forceinline__ void ldmx4(uint32_t& r0, uint32_t& r1, uint32_t& r2, uint32_t& r3,
                                      uint32_t addr) {
    asm volatile("ldmatrix.sync.aligned.m8n8.x4.shared.b16 {%0,%1,%2,%3}, [%4];"
                 : "=r"(r0), "=r"(r1), "=r"(r2), "=r"(r3) : "r"(addr));
}
__device__ __forceinline__ void mma16816(float& c0, float& c1, float& c2, float& c3,
                                         uint32_t a0, uint32_t a1, uint32_t a2, uint32_t a3,
                                         uint32_t b0, uint32_t b1) {
    asm volatile(
        "mma.sync.aligned.m16n8k16.row.col.f32.f16.f16.f32 "
        "{%0,%1,%2,%3}, {%4,%5,%6,%7}, {%8,%9}, {%0,%1,%2,%3};"
        : "+f"(c0), "+f"(c1), "+f"(c2), "+f"(c3)
        : "r"(a0), "r"(a1), "r"(a2), "r"(a3), "r"(b0), "r"(b1));
}

// ===================== kernel 1: prep v4 (coalesced spline stores) =====================
static constexpr int WPACK_BLOCKS = (NOUT * (NK / 8)) / 256;   // 4608  (4 pairs/thread)
static constexpr int ACT_BLOCKS   = NB;                        // 8192  (1 row per block)

__global__ void kan_prep(const float* __restrict__ x,
                         const float* __restrict__ bw,
                         const float* __restrict__ sw) {
    if (blockIdx.x < WPACK_BLOCKS) {
        // ---- pack weights, 8 consecutive K-elements per thread ----
        // g_Wh[o,0:1024]=bw[o,:]; g_Wh[o,1024+i*8+g]=sw[o,i,g]
        constexpr int QK = NK / 8;                       // 1152 octets per row
        int p = blockIdx.x * blockDim.x + threadIdx.x;
        int o  = p / QK;
        int kk = (p - o * QK) * 8;                       // multiple of 8; regions align
        const float* src = (kk < NIN)
            ? bw + (size_t)o * NIN + kk
            : sw + (size_t)o * (NIN * COEF) + (kk - NIN);
        float4 f0 = *reinterpret_cast<const float4*>(src);
        float4 f1 = *reinterpret_cast<const float4*>(src + 4);
        __half2 h0 = __floats2half2_rn(f0.x, f0.y);
        __half2 h1 = __floats2half2_rn(f0.z, f0.w);
        __half2 h2 = __floats2half2_rn(f1.x, f1.y);
        __half2 h3 = __floats2half2_rn(f1.z, f1.w);
        uint4 u;
        u.x = *reinterpret_cast<uint32_t*>(&h0);
        u.y = *reinterpret_cast<uint32_t*>(&h1);
        u.z = *reinterpret_cast<uint32_t*>(&h2);
        u.w = *reinterpret_cast<uint32_t*>(&h3);
        *reinterpret_cast<uint4*>(g_Wh + (size_t)o * NK + kk) = u;
        return;
    }
    // ---- activations: one batch row per block; thread t handles inputs
    //      {t, t+256, t+512, t+768} so every spline STG.128 is lane-contiguous ----
    const int b = blockIdx.x - WPACK_BLOCKS;
    const int t = threadIdx.x;
    const float* xrow = x + (size_t)b * NIN;
    const size_t ro = (size_t)b * NK;
    __half* silu_dst = g_Ah + ro;
    __half* base_dst = g_Ah + ro + NIN;

#pragma unroll
    for (int e = 0; e < 4; ++e) {
        const int i = t + e * 256;
        const float v = xrow[i];

        // silu: 2B store, lanes contiguous (64B/warp)
        silu_dst[i] = __float2half_rn(v / (1.0f + __expf(-v)));

        // uniform cubic B-spline bases: 4 nonzero values at slots j..j+3 of 8.
        // Pack (n0..n3) into 64-bit P and shift left by 16*j within a 128-bit lane.
        float xs = v * 5.0f;
        int j = __float2int_rd(xs);       // x in [0,1) -> j in [0,4]
        j = (j > 4) ? 4 : ((j < 0) ? 0 : j);
        float tt = xs - (float)j;
        float t2 = tt * tt, omt = 1.0f - tt;
        // Horner forms of the uniform cubic B-spline basis values
        float n0 = omt * omt * omt * (1.0f / 6.0f);
        float n1 = (0.5f * tt - 1.0f) * t2 + (2.0f / 3.0f);
        float n2 = ((-0.5f * tt + 0.5f) * tt + 0.5f) * tt + (1.0f / 6.0f);
        float n3 = tt * t2 * (1.0f / 6.0f);

        __half2 q01 = __floats2half2_rn(n0, n1);
        __half2 q23 = __floats2half2_rn(n2, n3);
        uint64_t P = (uint64_t)(*reinterpret_cast<uint32_t*>(&q01))
                   | ((uint64_t)(*reinterpret_cast<uint32_t*>(&q23)) << 32);
        const int sh = j * 16;
        uint64_t lo, hi;
        if (j == 0)      { lo = P;        hi = 0; }
        else if (j < 4)  { lo = P << sh;  hi = P >> (64 - sh); }
        else             { lo = 0;        hi = P; }
        uint4 u;
        u.x = (uint32_t)lo;  u.y = (uint32_t)(lo >> 32);
        u.z = (uint32_t)hi;  u.w = (uint32_t)(hi >> 32);
        // lane-contiguous: input i -> byte offset i*16 in the spline region
        *reinterpret_cast<uint4*>(base_dst + (size_t)i * 8) = u;
    }
}

// ===================== kernel 2: persistent split-K HMMA GEMM (unchanged from R10) =====
__global__ void __launch_bounds__(256, 1) kan_gemm(float* __restrict__ out) {
    extern __shared__ __align__(1024) char smem[];
    const uint32_t sb = smem_u32(smem);
    const uint32_t sbA = sb;
    const uint32_t sbB = sb + STAGES * A_TILE;

    const int tid = threadIdx.x;
    const int lane = tid & 31;
    const int wid = tid >> 5;
    const int wm = wid & 3;          // 4 warps along M (64 rows each)
    const int wn = wid >> 2;         // 2 warps along N (64 cols each)

    const int c = blockIdx.x;
    const int u0 = c * U_BASE + (c < U_REM ? c : U_REM);
    const int u1 = u0 + U_BASE + (c < U_REM ? 1 : 0);

    int lt = u0 / KT_PER_TILE, lkt = u0 - lt * KT_PER_TILE;
    int ct = lt, ckt = lkt;

    auto load_stage = [&](int s, int t, int kt) {
        const int m0 = (t >> 3) * BM;
        const int n0 = (t & 7) * BN;
        const char* gA = (const char*)(g_Ah) + ((size_t)m0 * NK) * 2;
        const char* gB = (const char*)(g_Wh) + ((size_t)n0 * NK) * 2;
        const uint32_t dA = sbA + (uint32_t)s * A_TILE;
        const uint32_t dB = sbB + (uint32_t)s * B_TILE;
        const size_t koff = (size_t)kt * BK * 2;
#pragma unroll
        for (int i = 0; i < 16; ++i) {
            int cc = tid + i * 256;
            int row = cc >> 4, col = cc & 15;
            uint32_t doff = (uint32_t)(col >> 3) * A_SUB + ((uint32_t)row << 7)
                          + (((uint32_t)(col & 7) ^ (uint32_t)(row & 7)) << 4);
            cp16(dA + doff, gA + (size_t)row * (NK * 2) + koff + (size_t)col * 16);
        }
#pragma unroll
        for (int i = 0; i < 8; ++i) {
            int cc = tid + i * 256;
            int row = cc >> 4, col = cc & 15;
            uint32_t doff = (uint32_t)(col >> 3) * B_SUB + ((uint32_t)row << 7)
                          + (((uint32_t)(col & 7) ^ (uint32_t)(row & 7)) << 4);
            cp16(dB + doff, gB + (size_t)row * (NK * 2) + koff + (size_t)col * 16);
        }
    };

    load_stage(0, lt, lkt); CP_COMMIT();
    if (++lkt == KT_PER_TILE) { lkt = 0; ++lt; }

    float acc[4][8][4];
#pragma unroll
    for (int mi = 0; mi < 4; ++mi)
#pragma unroll
        for (int ni = 0; ni < 8; ++ni)
#pragma unroll
            for (int r = 0; r < 4; ++r) acc[mi][ni][r] = 0.0f;

    const int arow = wm * 64 + (lane & 15);
    const int brow = wn * 64 + (lane & 7) + ((lane >> 4) << 3);
    const uint32_t aPar  = (uint32_t)(arow & 7);
    const uint32_t bPar  = (uint32_t)(brow & 7);
    const uint32_t aKsel = (uint32_t)(lane >> 4);
    const uint32_t bKsel = (uint32_t)((lane >> 3) & 1);
    const uint32_t aBase = (uint32_t)arow << 7;
    const uint32_t bBase = (uint32_t)brow << 7;

    uint32_t fa[2][4][4];
    uint32_t fb[2][8][2];

    auto load_frags = [&](int buf, uint32_t tAs, uint32_t tBs, int ks) {
        const uint32_t aChunk = (((uint32_t)(ks * 2) + aKsel) ^ aPar) << 4;
#pragma unroll
        for (int mi = 0; mi < 4; ++mi)
            ldmx4(fa[buf][mi][0], fa[buf][mi][1], fa[buf][mi][2], fa[buf][mi][3],
                  tAs + aBase + ((uint32_t)mi << 11) + aChunk);
        const uint32_t bChunk = (((uint32_t)(ks * 2) + bKsel) ^ bPar) << 4;
#pragma unroll
        for (int g = 0; g < 4; ++g) {
            uint32_t q0, q1, q2, q3;
            ldmx4(q0, q1, q2, q3, tBs + bBase + ((uint32_t)g << 11) + bChunk);
            fb[buf][g * 2 + 0][0] = q0; fb[buf][g * 2 + 0][1] = q1;
            fb[buf][g * 2 + 1][0] = q2; fb[buf][g * 2 + 1][1] = q3;
        }
    };
    auto mma_block = [&](int buf) {
#pragma unroll
        for (int mi = 0; mi < 4; ++mi)
#pragma unroll
            for (int ni = 0; ni < 8; ++ni)
                mma16816(acc[mi][ni][0], acc[mi][ni][1], acc[mi][ni][2], acc[mi][ni][3],
                         fa[buf][mi][0], fa[buf][mi][1], fa[buf][mi][2], fa[buf][mi][3],
                         fb[buf][ni][0], fb[buf][ni][1]);
    };

    const int q = lane >> 2, p = lane & 3;
    auto dump = [&](int t, bool full) {
        if (full) {
            const int m0 = (t >> 3) * BM;
            const int n0 = (t & 7) * BN;
#pragma unroll
            for (int mi = 0; mi < 4; ++mi) {
                int mbase = m0 + wm * 64 + mi * 16 + q;
#pragma unroll
                for (int ni = 0; ni < 8; ++ni) {
                    int nbase = n0 + wn * 64 + ni * 8 + p * 2;
                    *reinterpret_cast<float2*>(out + (size_t)mbase * NOUT + nbase) =
                        make_float2(acc[mi][ni][0], acc[mi][ni][1]);
                    *reinterpret_cast<float2*>(out + (size_t)(mbase + 8) * NOUT + nbase) =
                        make_float2(acc[mi][ni][2], acc[mi][ni][3]);
                }
            }
        } else {
            const int slot = (t * KT_PER_TILE < u0) ? 0 : 1;   // head : tail
            float* pd = g_part[c][slot];
#pragma unroll
            for (int mi = 0; mi < 4; ++mi) {
                int mrel = wm * 64 + mi * 16 + q;
#pragma unroll
                for (int ni = 0; ni < 8; ++ni) {
                    int nrel = wn * 64 + ni * 8 + p * 2;
                    *reinterpret_cast<float2*>(pd + (size_t)mrel * BN + nrel) =
                        make_float2(acc[mi][ni][0], acc[mi][ni][1]);
                    *reinterpret_cast<float2*>(pd + (size_t)(mrel + 8) * BN + nrel) =
                        make_float2(acc[mi][ni][2], acc[mi][ni][3]);
                }
            }
        }
#pragma unroll
        for (int mi = 0; mi < 4; ++mi)
#pragma unroll
            for (int ni = 0; ni < 8; ++ni)
#pragma unroll
                for (int r = 0; r < 4; ++r) acc[mi][ni][r] = 0.0f;
    };

    int s = 0;
    for (int u = u0; u < u1; ++u) {
        CP_WAIT0();
        __syncthreads();

        if (u + 1 < u1) {
            load_stage(s ^ 1, lt, lkt); CP_COMMIT();
            if (++lkt == KT_PER_TILE) { lkt = 0; ++lt; }
        }

        const uint32_t tA = sbA + (uint32_t)s * A_TILE;
        const uint32_t tB = sbB + (uint32_t)s * B_TILE;

        load_frags(0, tA, tB, 0);
#pragma unroll
        for (int k8 = 0; k8 < 8; ++k8) {
            const int nk = k8 + 1;
            if (nk < 8)
                load_frags(nk & 1,
                           tA + (uint32_t)(nk >> 2) * A_SUB,
                           tB + (uint32_t)(nk >> 2) * B_SUB,
                           nk & 3);
            mma_block(k8 & 1);
        }
        s ^= 1;

        const bool tile_end  = (ckt == KT_PER_TILE - 1);
        const bool range_end = (u + 1 == u1);
        if (tile_end || range_end)
            dump(ct, tile_end && (ct * KT_PER_TILE >= u0));

        if (++ckt == KT_PER_TILE) { ckt = 0; ++ct; }
    }
}

// ===================== kernel 3: deterministic reduce of split tiles (unchanged) =======
__global__ void kan_reduce(float* __restrict__ out) {
    const int c = blockIdx.x + 1;
    const int u = c * U_BASE + (c < U_REM ? c : U_REM);
    const int kt = u % KT_PER_TILE;
    if (kt == 0) return;
    const int t = u / KT_PER_TILE;
    const int m0 = (t >> 3) * BM;
    const int n0 = (t & 7) * BN;
    const float4* pa = reinterpret_cast<const float4*>(g_part[c - 1][1]);
    const float4* pb = reinterpret_cast<const float4*>(g_part[c][0]);
    for (int i = threadIdx.x; i < (BM * BN) / 4; i += blockDim.x) {
        float4 va = pa[i], vb = pb[i];
        int e = i * 4;
        int r = e >> 7;
        int col = e & (BN - 1);
        float4 v = make_float4(va.x + vb.x, va.y + vb.y, va.z + vb.z, va.w + vb.w);
        *reinterpret_cast<float4*>(out + (size_t)(m0 + r) * NOUT + n0 + col) = v;
    }
}

// ===================== host launcher =====================
extern "C" void kernel_launch(void* const* d_in, const int* in_sizes, int n_in,
                              void* d_out, int out_size) {
    const float* x  = (const float*)d_in[0];
    const float* bw = (const float*)d_in[1];
    const float* sw = (const float*)d_in[2];
    float* out = (float*)d_out;

    cudaFuncSetAttribute(kan_gemm, cudaFuncAttributeMaxDynamicSharedMemorySize,
                         (int)SMEM_TOTAL);

    kan_prep<<<WPACK_BLOCKS + ACT_BLOCKS, 256>>>(x, bw, sw);
    kan_gemm<<<NCTA, 256, SMEM_TOTAL>>>(out);
    kan_reduce<<<NCTA - 1, 256>>>(out);
}

// round 14
// speedup vs baseline: 1.1073x; 1.0163x over previous
#include <cuda_runtime.h>
#include <cuda_fp16.h>
#include <cstdint>
#include <cstddef>

// ===================== problem constants =====================
static constexpr int NB   = 8192;               // batch
static constexpr int NIN  = 1024;               // in features
static constexpr int NOUT = 1024;               // out features
static constexpr int COEF = 8;                  // grid_size + spline_order
static constexpr int NK   = NIN + NIN * COEF;   // 9216 fused K

// ===================== gemm tiling =====================
static constexpr int BM = 256;
static constexpr int BN = 128;
static constexpr int BK = 128;                  // two 64-half sub-tiles per stage
static constexpr int KT_PER_TILE = NK / BK;     // 72
static constexpr int STAGES = 2;

static constexpr uint32_t A_SUB  = (uint32_t)BM * 64 * 2;      // 32768
static constexpr uint32_t B_SUB  = (uint32_t)BN * 64 * 2;      // 16384
static constexpr uint32_t A_TILE = 2 * A_SUB;                  // 65536
static constexpr uint32_t B_TILE = 2 * B_SUB;                  // 32768
static constexpr uint32_t SMEM_TOTAL = STAGES * (A_TILE + B_TILE); // 196608

// ===================== persistent split-K schedule =====================
static constexpr int NTILES  = (NB / BM) * (NOUT / BN);        // 256 output tiles
static constexpr int TOTAL_U = NTILES * KT_PER_TILE;           // 18432 (tile,kt) units
static constexpr int NCTA    = 148;                            // 1 CTA per SM
static constexpr int U_BASE  = TOTAL_U / NCTA;                 // 124
static constexpr int U_REM   = TOTAL_U % NCTA;                 // 80 CTAs get +1

// ===================== device scratch (no allocations allowed) =====================
__device__ __align__(1024) __half g_Ah[(size_t)NB * NK];       // ~151 MB fp16 activations
__device__ __align__(1024) __half g_Wh[(size_t)NOUT * NK];     // ~19 MB fp16 packed weights
__device__ __align__(1024) float  g_part[NCTA][2][BM * BN];    // ~39 MB split-tile partials

// ===================== helpers =====================
__device__ __forceinline__ uint32_t smem_u32(const void* p) {
    uint32_t a;
    asm("{ .reg .u64 t; cvta.to.shared.u64 t, %1; cvt.u32.u64 %0, t; }" : "=r"(a) : "l"(p));
    return a;
}
__device__ __forceinline__ void cp16(uint32_t dst, const void* src) {
    asm volatile("cp.async.cg.shared.global [%0], [%1], 16;" :: "r"(dst), "l"(src) : "memory");
}
#define CP_COMMIT() asm volatile("cp.async.commit_group;" ::: "memory")
#define CP_WAIT0()  asm volatile("cp.async.wait_group 0;" ::: "memory")

__device__ __forceinline__ void ldmx4(uint32_t& r0, uint32_t& r1, uint32_t& r2, uint32_t& r3,
                                      uint32_t addr) {
    asm volatile("ldmatrix.sync.aligned.m8n8.x4.shared.b16 {%0,%1,%2,%3}, [%4];"
                 : "=r"(r0), "=r"(r1), "=r"(r2), "=r"(r3) : "r"(addr));
}
__device__ __forceinline__ void mma16816(float& c0, float& c1, float& c2, float& c3,
                                         uint32_t a0, uint32_t a1, uint32_t a2, uint32_t a3,
                                         uint32_t b0, uint32_t b1) {
    asm volatile(
        "mma.sync.aligned.m16n8k16.row.col.f32.f16.f16.f32 "
        "{%0,%1,%2,%3}, {%4,%5,%6,%7}, {%8,%9}, {%0,%1,%2,%3};"
        : "+f"(c0), "+f"(c1), "+f"(c2), "+f"(c3)
        : "r"(a0), "r"(a1), "r"(a2), "r"(a3), "r"(b0), "r"(b1));
}

// ===================== kernel 1: prep v5 (batched loads + fast-div silu) ===============
static constexpr int WPACK_BLOCKS = (NOUT * (NK / 8)) / 256;   // 4608  (4 pairs/thread)
static constexpr int ACT_BLOCKS   = NB;                        // 8192  (1 row per block)

__global__ void kan_prep(const float* __restrict__ x,
                         const float* __restrict__ bw,
                         const float* __restrict__ sw) {
    if (blockIdx.x < WPACK_BLOCKS) {
        // ---- pack weights, 8 consecutive K-elements per thread ----
        // g_Wh[o,0:1024]=bw[o,:]; g_Wh[o,1024+i*8+g]=sw[o,i,g]
        constexpr int QK = NK / 8;                       // 1152 octets per row
        int p = blockIdx.x * blockDim.x + threadIdx.x;
        int o  = p / QK;
        int kk = (p - o * QK) * 8;                       // multiple of 8; regions align
        const float* src = (kk < NIN)
            ? bw + (size_t)o * NIN + kk
            : sw + (size_t)o * (NIN * COEF) + (kk - NIN);
        float4 f0 = *reinterpret_cast<const float4*>(src);
        float4 f1 = *reinterpret_cast<const float4*>(src + 4);
        __half2 h0 = __floats2half2_rn(f0.x, f0.y);
        __half2 h1 = __floats2half2_rn(f0.z, f0.w);
        __half2 h2 = __floats2half2_rn(f1.x, f1.y);
        __half2 h3 = __floats2half2_rn(f1.z, f1.w);
        uint4 u;
        u.x = *reinterpret_cast<uint32_t*>(&h0);
        u.y = *reinterpret_cast<uint32_t*>(&h1);
        u.z = *reinterpret_cast<uint32_t*>(&h2);
        u.w = *reinterpret_cast<uint32_t*>(&h3);
        *reinterpret_cast<uint4*>(g_Wh + (size_t)o * NK + kk) = u;
        return;
    }
    // ---- activations: one batch row per block; thread t handles inputs
    //      {t, t+256, t+512, t+768} so every spline STG.128 is lane-contiguous ----
    const int b = blockIdx.x - WPACK_BLOCKS;
    const int t = threadIdx.x;
    const float* xrow = x + (size_t)b * NIN;
    const size_t ro = (size_t)b * NK;
    __half* silu_dst = g_Ah + ro;
    __half* base_dst = g_Ah + ro + NIN;

    // batch all 4 loads up front: guaranteed MLP=4 before the compute chains
    float v[4];
#pragma unroll
    for (int e = 0; e < 4; ++e) v[e] = xrow[t + e * 256];

#pragma unroll
    for (int e = 0; e < 4; ++e) {
        const int i = t + e * 256;
        const float ve = v[e];

        // silu via fast exp + fast divide (1 MUFU.EX2 + 1 MUFU.RCP + muls)
        float s = __fdividef(ve, 1.0f + __expf(-ve));
        silu_dst[i] = __float2half_rn(s);

        // uniform cubic B-spline bases: 4 nonzero values at slots j..j+3 of 8.
        // Pack (n0..n3) into 64-bit P and shift left by 16*j within a 128-bit lane.
        float xs = ve * 5.0f;
        int j = __float2int_rd(xs);       // x in [0,1) -> j in [0,4]
        j = (j > 4) ? 4 : ((j < 0) ? 0 : j);
        float tt = xs - (float)j;
        float t2 = tt * tt, omt = 1.0f - tt;
        // Horner forms of the uniform cubic B-spline basis values
        float n0 = omt * omt * omt * (1.0f / 6.0f);
        float n1 = (0.5f * tt - 1.0f) * t2 + (2.0f / 3.0f);
        float n2 = ((-0.5f * tt + 0.5f) * tt + 0.5f) * tt + (1.0f / 6.0f);
        float n3 = tt * t2 * (1.0f / 6.0f);

        __half2 q01 = __floats2half2_rn(n0, n1);
        __half2 q23 = __floats2half2_rn(n2, n3);
        uint64_t P = (uint64_t)(*reinterpret_cast<uint32_t*>(&q01))
                   | ((uint64_t)(*reinterpret_cast<uint32_t*>(&q23)) << 32);
        const int sh = j * 16;
        uint64_t lo, hi;
        if (j == 0)      { lo = P;        hi = 0; }
        else if (j < 4)  { lo = P << sh;  hi = P >> (64 - sh); }
        else             { lo = 0;        hi = P; }
        uint4 u;
        u.x = (uint32_t)lo;  u.y = (uint32_t)(lo >> 32);
        u.z = (uint32_t)hi;  u.w = (uint32_t)(hi >> 32);
        // lane-contiguous: input i -> byte offset i*16 in the spline region
        *reinterpret_cast<uint4*>(base_dst + (size_t)i * 8) = u;
    }
}

// ===================== kernel 2: persistent split-K HMMA GEMM (unchanged from R10) =====
__global__ void __launch_bounds__(256, 1) kan_gemm(float* __restrict__ out) {
    extern __shared__ __align__(1024) char smem[];
    const uint32_t sb = smem_u32(smem);
    const uint32_t sbA = sb;
    const uint32_t sbB = sb + STAGES * A_TILE;

    const int tid = threadIdx.x;
    const int lane = tid & 31;
    const int wid = tid >> 5;
    const int wm = wid & 3;          // 4 warps along M (64 rows each)
    const int wn = wid >> 2;         // 2 warps along N (64 cols each)

    const int c = blockIdx.x;
    const int u0 = c * U_BASE + (c < U_REM ? c : U_REM);
    const int u1 = u0 + U_BASE + (c < U_REM ? 1 : 0);

    int lt = u0 / KT_PER_TILE, lkt = u0 - lt * KT_PER_TILE;
    int ct = lt, ckt = lkt;

    auto load_stage = [&](int s, int t, int kt) {
        const int m0 = (t >> 3) * BM;
        const int n0 = (t & 7) * BN;
        const char* gA = (const char*)(g_Ah) + ((size_t)m0 * NK) * 2;
        const char* gB = (const char*)(g_Wh) + ((size_t)n0 * NK) * 2;
        const uint32_t dA = sbA + (uint32_t)s * A_TILE;
        const uint32_t dB = sbB + (uint32_t)s * B_TILE;
        const size_t koff = (size_t)kt * BK * 2;
#pragma unroll
        for (int i = 0; i < 16; ++i) {
            int cc = tid + i * 256;
            int row = cc >> 4, col = cc & 15;
            uint32_t doff = (uint32_t)(col >> 3) * A_SUB + ((uint32_t)row << 7)
                          + (((uint32_t)(col & 7) ^ (uint32_t)(row & 7)) << 4);
            cp16(dA + doff, gA + (size_t)row * (NK * 2) + koff + (size_t)col * 16);
        }
#pragma unroll
        for (int i = 0; i < 8; ++i) {
            int cc = tid + i * 256;
            int row = cc >> 4, col = cc & 15;
            uint32_t doff = (uint32_t)(col >> 3) * B_SUB + ((uint32_t)row << 7)
                          + (((uint32_t)(col & 7) ^ (uint32_t)(row & 7)) << 4);
            cp16(dB + doff, gB + (size_t)row * (NK * 2) + koff + (size_t)col * 16);
        }
    };

    load_stage(0, lt, lkt); CP_COMMIT();
    if (++lkt == KT_PER_TILE) { lkt = 0; ++lt; }

    float acc[4][8][4];
#pragma unroll
    for (int mi = 0; mi < 4; ++mi)
#pragma unroll
        for (int ni = 0; ni < 8; ++ni)
#pragma unroll
            for (int r = 0; r < 4; ++r) acc[mi][ni][r] = 0.0f;

    const int arow = wm * 64 + (lane & 15);
    const int brow = wn * 64 + (lane & 7) + ((lane >> 4) << 3);
    const uint32_t aPar  = (uint32_t)(arow & 7);
    const uint32_t bPar  = (uint32_t)(brow & 7);
    const uint32_t aKsel = (uint32_t)(lane >> 4);
    const uint32_t bKsel = (uint32_t)((lane >> 3) & 1);
    const uint32_t aBase = (uint32_t)arow << 7;
    const uint32_t bBase = (uint32_t)brow << 7;

    uint32_t fa[2][4][4];
    uint32_t fb[2][8][2];

    auto load_frags = [&](int buf, uint32_t tAs, uint32_t tBs, int ks) {
        const uint32_t aChunk = (((uint32_t)(ks * 2) + aKsel) ^ aPar) << 4;
#pragma unroll
        for (int mi = 0; mi < 4; ++mi)
            ldmx4(fa[buf][mi][0], fa[buf][mi][1], fa[buf][mi][2], fa[buf][mi][3],
                  tAs + aBase + ((uint32_t)mi << 11) + aChunk);
        const uint32_t bChunk = (((uint32_t)(ks * 2) + bKsel) ^ bPar) << 4;
#pragma unroll
        for (int g = 0; g < 4; ++g) {
            uint32_t q0, q1, q2, q3;
            ldmx4(q0, q1, q2, q3, tBs + bBase + ((uint32_t)g << 11) + bChunk);
            fb[buf][g * 2 + 0][0] = q0; fb[buf][g * 2 + 0][1] = q1;
            fb[buf][g * 2 + 1][0] = q2; fb[buf][g * 2 + 1][1] = q3;
        }
    };
    auto mma_block = [&](int buf) {
#pragma unroll
        for (int mi = 0; mi < 4; ++mi)
#pragma unroll
            for (int ni = 0; ni < 8; ++ni)
                mma16816(acc[mi][ni][0], acc[mi][ni][1], acc[mi][ni][2], acc[mi][ni][3],
                         fa[buf][mi][0], fa[buf][mi][1], fa[buf][mi][2], fa[buf][mi][3],
                         fb[buf][ni][0], fb[buf][ni][1]);
    };

    const int q = lane >> 2, p = lane & 3;
    auto dump = [&](int t, bool full) {
        if (full) {
            const int m0 = (t >> 3) * BM;
            const int n0 = (t & 7) * BN;
#pragma unroll
            for (int mi = 0; mi < 4; ++mi) {
                int mbase = m0 + wm * 64 + mi * 16 + q;
#pragma unroll
                for (int ni = 0; ni < 8; ++ni) {
                    int nbase = n0 + wn * 64 + ni * 8 + p * 2;
                    *reinterpret_cast<float2*>(out + (size_t)mbase * NOUT + nbase) =
                        make_float2(acc[mi][ni][0], acc[mi][ni][1]);
                    *reinterpret_cast<float2*>(out + (size_t)(mbase + 8) * NOUT + nbase) =
                        make_float2(acc[mi][ni][2], acc[mi][ni][3]);
                }
            }
        } else {
            const int slot = (t * KT_PER_TILE < u0) ? 0 : 1;   // head : tail
            float* pd = g_part[c][slot];
#pragma unroll
            for (int mi = 0; mi < 4; ++mi) {
                int mrel = wm * 64 + mi * 16 + q;
#pragma unroll
                for (int ni = 0; ni < 8; ++ni) {
                    int nrel = wn * 64 + ni * 8 + p * 2;
                    *reinterpret_cast<float2*>(pd + (size_t)mrel * BN + nrel) =
                        make_float2(acc[mi][ni][0], acc[mi][ni][1]);
                    *reinterpret_cast<float2*>(pd + (size_t)(mrel + 8) * BN + nrel) =
                        make_float2(acc[mi][ni][2], acc[mi][ni][3]);
                }
            }
        }
#pragma unroll
        for (int mi = 0; mi < 4; ++mi)
#pragma unroll
            for (int ni = 0; ni < 8; ++ni)
#pragma unroll
                for (int r = 0; r < 4; ++r) acc[mi][ni][r] = 0.0f;
    };

    int s = 0;
    for (int u = u0; u < u1; ++u) {
        CP_WAIT0();
        __syncthreads();

        if (u + 1 < u1) {
            load_stage(s ^ 1, lt, lkt); CP_COMMIT();
            if (++lkt == KT_PER_TILE) { lkt = 0; ++lt; }
        }

        const uint32_t tA = sbA + (uint32_t)s * A_TILE;
        const uint32_t tB = sbB + (uint32_t)s * B_TILE;

        load_frags(0, tA, tB, 0);
#pragma unroll
        for (int k8 = 0; k8 < 8; ++k8) {
            const int nk = k8 + 1;
            if (nk < 8)
                load_frags(nk & 1,
                           tA + (uint32_t)(nk >> 2) * A_SUB,
                           tB + (uint32_t)(nk >> 2) * B_SUB,
                           nk & 3);
            mma_block(k8 & 1);
        }
        s ^= 1;

        const bool tile_end  = (ckt == KT_PER_TILE - 1);
        const bool range_end = (u + 1 == u1);
        if (tile_end || range_end)
            dump(ct, tile_end && (ct * KT_PER_TILE >= u0));

        if (++ckt == KT_PER_TILE) { ckt = 0; ++ct; }
    }
}

// ===================== kernel 3: deterministic reduce of split tiles (unchanged) =======
__global__ void kan_reduce(float* __restrict__ out) {
    const int c = blockIdx.x + 1;
    const int u = c * U_BASE + (c < U_REM ? c : U_REM);
    const int kt = u % KT_PER_TILE;
    if (kt == 0) return;
    const int t = u / KT_PER_TILE;
    const int m0 = (t >> 3) * BM;
    const int n0 = (t & 7) * BN;
    const float4* pa = reinterpret_cast<const float4*>(g_part[c - 1][1]);
    const float4* pb = reinterpret_cast<const float4*>(g_part[c][0]);
    for (int i = threadIdx.x; i < (BM * BN) / 4; i += blockDim.x) {
        float4 va = pa[i], vb = pb[i];
        int e = i * 4;
        int r = e >> 7;
        int col = e & (BN - 1);
        float4 v = make_float4(va.x + vb.x, va.y + vb.y, va.z + vb.z, va.w + vb.w);
        *reinterpret_cast<float4*>(out + (size_t)(m0 + r) * NOUT + n0 + col) = v;
    }
}

// ===================== host launcher =====================
extern "C" void kernel_launch(void* const* d_in, const int* in_sizes, int n_in,
                              void* d_out, int out_size) {
    const float* x  = (const float*)d_in[0];
    const float* bw = (const float*)d_in[1];
    const float* sw = (const float*)d_in[2];
    float* out = (float*)d_out;

    cudaFuncSetAttribute(kan_gemm, cudaFuncAttributeMaxDynamicSharedMemorySize,
                         (int)SMEM_TOTAL);

    kan_prep<<<WPACK_BLOCKS + ACT_BLOCKS, 256>>>(x, bw, sw);
    kan_gemm<<<NCTA, 256, SMEM_TOTAL>>>(out);
    kan_reduce<<<NCTA - 1, 256>>>(out);
}

// round 15
// speedup vs baseline: 1.1130x; 1.0051x over previous
#include <cuda_runtime.h>
#include <cuda_fp16.h>
#include <cstdint>
#include <cstddef>

// ===================== problem constants =====================
static constexpr int NB   = 8192;               // batch
static constexpr int NIN  = 1024;               // in features
static constexpr int NOUT = 1024;               // out features
static constexpr int COEF = 8;                  // grid_size + spline_order
static constexpr int NK   = NIN + NIN * COEF;   // 9216 fused K

// ===================== gemm tiling =====================
static constexpr int BM = 256;
static constexpr int BN = 128;
static constexpr int BK = 128;                  // two 64-half sub-tiles per stage
static constexpr int KT_PER_TILE = NK / BK;     // 72
static constexpr int STAGES = 2;

static constexpr uint32_t A_SUB  = (uint32_t)BM * 64 * 2;      // 32768
static constexpr uint32_t B_SUB  = (uint32_t)BN * 64 * 2;      // 16384
static constexpr uint32_t A_TILE = 2 * A_SUB;                  // 65536
static constexpr uint32_t B_TILE = 2 * B_SUB;                  // 32768
static constexpr uint32_t SMEM_TOTAL = STAGES * (A_TILE + B_TILE); // 196608

// ===================== persistent split-K schedule =====================
static constexpr int NTILES  = (NB / BM) * (NOUT / BN);        // 256 output tiles
static constexpr int TOTAL_U = NTILES * KT_PER_TILE;           // 18432 (tile,kt) units
static constexpr int NCTA    = 148;                            // 1 CTA per SM
static constexpr int U_BASE  = TOTAL_U / NCTA;                 // 124
static constexpr int U_REM   = TOTAL_U % NCTA;                 // 80 CTAs get +1

// ===================== device scratch (no allocations allowed) =====================
__device__ __align__(1024) __half g_Ah[(size_t)NB * NK];       // ~151 MB fp16 activations
__device__ __align__(1024) __half g_Wh[(size_t)NOUT * NK];     // ~19 MB fp16 packed weights
__device__ __align__(1024) float  g_part[NCTA][2][BM * BN];    // ~39 MB split-tile partials

// ===================== helpers =====================
__device__ __forceinline__ uint32_t smem_u32(const void* p) {
    uint32_t a;
    asm("{ .reg .u64 t; cvta.to.shared.u64 t, %1; cvt.u32.u64 %0, t; }" : "=r"(a) : "l"(p));
    return a;
}
__device__ __forceinline__ void cp16(uint32_t dst, const void* src) {
    asm volatile("cp.async.cg.shared.global [%0], [%1], 16;" :: "r"(dst), "l"(src) : "memory");
}
#define CP_COMMIT() asm volatile("cp.async.commit_group;" ::: "memory")
#define CP_WAIT0()  asm volatile("cp.async.wait_group 0;" ::: "memory")

__device__ __forceinline__ void ldmx4(uint32_t& r0, uint32_t& r1, uint32_t& r2, uint32_t& r3,
                                      uint32_t addr) {
    asm volatile("ldmatrix.sync.aligned.m8n8.x4.shared.b16 {%0,%1,%2,%3}, [%4];"
                 : "=r"(r0), "=r"(r1), "=r"(r2), "=r"(r3) : "r"(addr));
}
__device__ __forceinline__ void mma16816(float& c0, float& c1, float& c2, float& c3,
                                         uint32_t a0, uint32_t a1, uint32_t a2, uint32_t a3,
                                         uint32_t b0, uint32_t b1) {
    asm volatile(
        "mma.sync.aligned.m16n8k16.row.col.f32.f16.f16.f32 "
        "{%0,%1,%2,%3}, {%4,%5,%6,%7}, {%8,%9}, {%0,%1,%2,%3};"
        : "+f"(c0), "+f"(c1), "+f"(c2), "+f"(c3)
        : "r"(a0), "r"(a1), "r"(a2), "r"(a3), "r"(b0), "r"(b1));
}

// ===================== kernel 1: prep v6 (branchless 128-bit spline shift) =============
static constexpr int WPACK_BLOCKS = (NOUT * (NK / 8)) / 256;   // 4608  (4 pairs/thread)
static constexpr int ACT_BLOCKS   = NB;                        // 8192  (1 row per block)

__global__ void kan_prep(const float* __restrict__ x,
                         const float* __restrict__ bw,
                         const float* __restrict__ sw) {
    if (blockIdx.x < WPACK_BLOCKS) {
        // ---- pack weights, 8 consecutive K-elements per thread ----
        // g_Wh[o,0:1024]=bw[o,:]; g_Wh[o,1024+i*8+g]=sw[o,i,g]
        constexpr int QK = NK / 8;                       // 1152 octets per row
        int p = blockIdx.x * blockDim.x + threadIdx.x;
        int o  = p / QK;
        int kk = (p - o * QK) * 8;                       // multiple of 8; regions align
        const float* src = (kk < NIN)
            ? bw + (size_t)o * NIN + kk
            : sw + (size_t)o * (NIN * COEF) + (kk - NIN);
        float4 f0 = *reinterpret_cast<const float4*>(src);
        float4 f1 = *reinterpret_cast<const float4*>(src + 4);
        __half2 h0 = __floats2half2_rn(f0.x, f0.y);
        __half2 h1 = __floats2half2_rn(f0.z, f0.w);
        __half2 h2 = __floats2half2_rn(f1.x, f1.y);
        __half2 h3 = __floats2half2_rn(f1.z, f1.w);
        uint4 u;
        u.x = *reinterpret_cast<uint32_t*>(&h0);
        u.y = *reinterpret_cast<uint32_t*>(&h1);
        u.z = *reinterpret_cast<uint32_t*>(&h2);
        u.w = *reinterpret_cast<uint32_t*>(&h3);
        *reinterpret_cast<uint4*>(g_Wh + (size_t)o * NK + kk) = u;
        return;
    }
    // ---- activations: one batch row per block; thread t handles inputs
    //      {t, t+256, t+512, t+768} so every spline STG.128 is lane-contiguous ----
    const int b = blockIdx.x - WPACK_BLOCKS;
    const int t = threadIdx.x;
    const float* xrow = x + (size_t)b * NIN;
    const size_t ro = (size_t)b * NK;
    __half* silu_dst = g_Ah + ro;
    __half* base_dst = g_Ah + ro + NIN;

    // batch all 4 loads up front: guaranteed MLP=4 before the compute chains
    float v[4];
#pragma unroll
    for (int e = 0; e < 4; ++e) v[e] = xrow[t + e * 256];

#pragma unroll
    for (int e = 0; e < 4; ++e) {
        const int i = t + e * 256;
        const float ve = v[e];

        // silu via fast exp + fast divide (1 MUFU.EX2 + 1 MUFU.RCP + muls)
        float s = __fdividef(ve, 1.0f + __expf(-ve));
        silu_dst[i] = __float2half_rn(s);

        // uniform cubic B-spline bases: 4 nonzero values at slots j..j+3 of 8.
        float xs = ve * 5.0f;
        int j = __float2int_rd(xs);       // x in [0,1) -> j in [0,4]
        j = (j > 4) ? 4 : ((j < 0) ? 0 : j);
        float tt = xs - (float)j;
        float t2 = tt * tt, omt = 1.0f - tt;
        // Horner forms of the uniform cubic B-spline basis values
        float n0 = omt * omt * omt * (1.0f / 6.0f);
        float n1 = (0.5f * tt - 1.0f) * t2 + (2.0f / 3.0f);
        float n2 = ((-0.5f * tt + 0.5f) * tt + 0.5f) * tt + (1.0f / 6.0f);
        float n3 = tt * t2 * (1.0f / 6.0f);

        __half2 q01 = __floats2half2_rn(n0, n1);
        __half2 q23 = __floats2half2_rn(n2, n3);
        const uint32_t a0 = *reinterpret_cast<uint32_t*>(&q01);
        const uint32_t a1 = *reinterpret_cast<uint32_t*>(&q23);

        // branchless 128-bit shift of 64-bit packet (a1:a0) left by j*16 bits:
        //   s16 = (j&1)*16 in {0,16}; wo = j>>1 in {0,1,2} word offset.
        // Verified per case: j=0 -> {a0,a1,0,0}; j=1 -> {a0<<16, fs(a0,a1,16), a1>>16, 0};
        // j=2 -> {0,a0,a1,0}; j=3 -> {0, a0<<16, fs, a1>>16}; j=4 -> {0,0,a0,a1}.
        const uint32_t s16 = (uint32_t)(j & 1) << 4;
        const int      wo  = j >> 1;
        const uint32_t p0 = a0 << s16;
        const uint32_t p1 = __funnelshift_l(a0, a1, s16);   // s=0 -> a1
        const uint32_t p2 = s16 ? (a1 >> 16) : 0u;
        uint4 u;
        u.x = (wo == 0) ? p0 : 0u;
        u.y = (wo == 0) ? p1 : ((wo == 1) ? p0 : 0u);
        u.z = (wo == 0) ? p2 : ((wo == 1) ? p1 : p0);
        u.w = (wo == 1) ? p2 : ((wo == 2) ? p1 : 0u);
        // lane-contiguous: input i -> byte offset i*16 in the spline region
        *reinterpret_cast<uint4*>(base_dst + (size_t)i * 8) = u;
    }
}

// ===================== kernel 2: persistent split-K HMMA GEMM (unchanged from R10) =====
__global__ void __launch_bounds__(256, 1) kan_gemm(float* __restrict__ out) {
    extern __shared__ __align__(1024) char smem[];
    const uint32_t sb = smem_u32(smem);
    const uint32_t sbA = sb;
    const uint32_t sbB = sb + STAGES * A_TILE;

    const int tid = threadIdx.x;
    const int lane = tid & 31;
    const int wid = tid >> 5;
    const int wm = wid & 3;          // 4 warps along M (64 rows each)
    const int wn = wid >> 2;         // 2 warps along N (64 cols each)

    const int c = blockIdx.x;
    const int u0 = c * U_BASE + (c < U_REM ? c : U_REM);
    const int u1 = u0 + U_BASE + (c < U_REM ? 1 : 0);

    int lt = u0 / KT_PER_TILE, lkt = u0 - lt * KT_PER_TILE;
    int ct = lt, ckt = lkt;

    auto load_stage = [&](int s, int t, int kt) {
        const int m0 = (t >> 3) * BM;
        const int n0 = (t & 7) * BN;
        const char* gA = (const char*)(g_Ah) + ((size_t)m0 * NK) * 2;
        const char* gB = (const char*)(g_Wh) + ((size_t)n0 * NK) * 2;
        const uint32_t dA = sbA + (uint32_t)s * A_TILE;
        const uint32_t dB = sbB + (uint32_t)s * B_TILE;
        const size_t koff = (size_t)kt * BK * 2;
#pragma unroll
        for (int i = 0; i < 16; ++i) {
            int cc = tid + i * 256;
            int row = cc >> 4, col = cc & 15;
            uint32_t doff = (uint32_t)(col >> 3) * A_SUB + ((uint32_t)row << 7)
                          + (((uint32_t)(col & 7) ^ (uint32_t)(row & 7)) << 4);
            cp16(dA + doff, gA + (size_t)row * (NK * 2) + koff + (size_t)col * 16);
        }
#pragma unroll
        for (int i = 0; i < 8; ++i) {
            int cc = tid + i * 256;
            int row = cc >> 4, col = cc & 15;
            uint32_t doff = (uint32_t)(col >> 3) * B_SUB + ((uint32_t)row << 7)
                          + (((uint32_t)(col & 7) ^ (uint32_t)(row & 7)) << 4);
            cp16(dB + doff, gB + (size_t)row * (NK * 2) + koff + (size_t)col * 16);
        }
    };

    load_stage(0, lt, lkt); CP_COMMIT();
    if (++lkt == KT_PER_TILE) { lkt = 0; ++lt; }

    float acc[4][8][4];
#pragma unroll
    for (int mi = 0; mi < 4; ++mi)
#pragma unroll
        for (int ni = 0; ni < 8; ++ni)
#pragma unroll
            for (int r = 0; r < 4; ++r) acc[mi][ni][r] = 0.0f;

    const int arow = wm * 64 + (lane & 15);
    const int brow = wn * 64 + (lane & 7) + ((lane >> 4) << 3);
    const uint32_t aPar  = (uint32_t)(arow & 7);
    const uint32_t bPar  = (uint32_t)(brow & 7);
    const uint32_t aKsel = (uint32_t)(lane >> 4);
    const uint32_t bKsel = (uint32_t)((lane >> 3) & 1);
    const uint32_t aBase = (uint32_t)arow << 7;
    const uint32_t bBase = (uint32_t)brow << 7;

    uint32_t fa[2][4][4];
    uint32_t fb[2][8][2];

    auto load_frags = [&](int buf, uint32_t tAs, uint32_t tBs, int ks) {
        const uint32_t aChunk = (((uint32_t)(ks * 2) + aKsel) ^ aPar) << 4;
#pragma unroll
        for (int mi = 0; mi < 4; ++mi)
            ldmx4(fa[buf][mi][0], fa[buf][mi][1], fa[buf][mi][2], fa[buf][mi][3],
                  tAs + aBase + ((uint32_t)mi << 11) + aChunk);
        const uint32_t bChunk = (((uint32_t)(ks * 2) + bKsel) ^ bPar) << 4;
#pragma unroll
        for (int g = 0; g < 4; ++g) {
            uint32_t q0, q1, q2, q3;
            ldmx4(q0, q1, q2, q3, tBs + bBase + ((uint32_t)g << 11) + bChunk);
            fb[buf][g * 2 + 0][0] = q0; fb[buf][g * 2 + 0][1] = q1;
            fb[buf][g * 2 + 1][0] = q2; fb[buf][g * 2 + 1][1] = q3;
        }
    };
    auto mma_block = [&](int buf) {
#pragma unroll
        for (int mi = 0; mi < 4; ++mi)
#pragma unroll
            for (int ni = 0; ni < 8; ++ni)
                mma16816(acc[mi][ni][0], acc[mi][ni][1], acc[mi][ni][2], acc[mi][ni][3],
                         fa[buf][mi][0], fa[buf][mi][1], fa[buf][mi][2], fa[buf][mi][3],
                         fb[buf][ni][0], fb[buf][ni][1]);
    };

    const int q = lane >> 2, p = lane & 3;
    auto dump = [&](int t, bool full) {
        if (full) {
            const int m0 = (t >> 3) * BM;
            const int n0 = (t & 7) * BN;
#pragma unroll
            for (int mi = 0; mi < 4; ++mi) {
                int mbase = m0 + wm * 64 + mi * 16 + q;
#pragma unroll
                for (int ni = 0; ni < 8; ++ni) {
                    int nbase = n0 + wn * 64 + ni * 8 + p * 2;
                    *reinterpret_cast<float2*>(out + (size_t)mbase * NOUT + nbase) =
                        make_float2(acc[mi][ni][0], acc[mi][ni][1]);
                    *reinterpret_cast<float2*>(out + (size_t)(mbase + 8) * NOUT + nbase) =
                        make_float2(acc[mi][ni][2], acc[mi][ni][3]);
                }
            }
        } else {
            const int slot = (t * KT_PER_TILE < u0) ? 0 : 1;   // head : tail
            float* pd = g_part[c][slot];
#pragma unroll
            for (int mi = 0; mi < 4; ++mi) {
                int mrel = wm * 64 + mi * 16 + q;
#pragma unroll
                for (int ni = 0; ni < 8; ++ni) {
                    int nrel = wn * 64 + ni * 8 + p * 2;
                    *reinterpret_cast<float2*>(pd + (size_t)mrel * BN + nrel) =
                        make_float2(acc[mi][ni][0], acc[mi][ni][1]);
                    *reinterpret_cast<float2*>(pd + (size_t)(mrel + 8) * BN + nrel) =
                        make_float2(acc[mi][ni][2], acc[mi][ni][3]);
                }
            }
        }
#pragma unroll
        for (int mi = 0; mi < 4; ++mi)
#pragma unroll
            for (int ni = 0; ni < 8; ++ni)
#pragma unroll
                for (int r = 0; r < 4; ++r) acc[mi][ni][r] = 0.0f;
    };

    int s = 0;
    for (int u = u0; u < u1; ++u) {
        CP_WAIT0();
        __syncthreads();

        if (u + 1 < u1) {
            load_stage(s ^ 1, lt, lkt); CP_COMMIT();
            if (++lkt == KT_PER_TILE) { lkt = 0; ++lt; }
        }

        const uint32_t tA = sbA + (uint32_t)s * A_TILE;
        const uint32_t tB = sbB + (uint32_t)s * B_TILE;

        load_frags(0, tA, tB, 0);
#pragma unroll
        for (int k8 = 0; k8 < 8; ++k8) {
            const int nk = k8 + 1;
            if (nk < 8)
                load_frags(nk & 1,
                           tA + (uint32_t)(nk >> 2) * A_SUB,
                           tB + (uint32_t)(nk >> 2) * B_SUB,
                           nk & 3);
            mma_block(k8 & 1);
        }
        s ^= 1;

        const bool tile_end  = (ckt == KT_PER_TILE - 1);
        const bool range_end = (u + 1 == u1);
        if (tile_end || range_end)
            dump(ct, tile_end && (ct * KT_PER_TILE >= u0));

        if (++ckt == KT_PER_TILE) { ckt = 0; ++ct; }
    }
}

// ===================== kernel 3: deterministic reduce of split tiles (unchanged) =======
__global__ void kan_reduce(float* __restrict__ out) {
    const int c = blockIdx.x + 1;
    const int u = c * U_BASE + (c < U_REM ? c : U_REM);
    const int kt = u % KT_PER_TILE;
    if (kt == 0) return;
    const int t = u / KT_PER_TILE;
    const int m0 = (t >> 3) * BM;
    const int n0 = (t & 7) * BN;
    const float4* pa = reinterpret_cast<const float4*>(g_part[c - 1][1]);
    const float4* pb = reinterpret_cast<const float4*>(g_part[c][0]);
    for (int i = threadIdx.x; i < (BM * BN) / 4; i += blockDim.x) {
        float4 va = pa[i], vb = pb[i];
        int e = i * 4;
        int r = e >> 7;
        int col = e & (BN - 1);
        float4 v = make_float4(va.x + vb.x, va.y + vb.y, va.z + vb.z, va.w + vb.w);
        *reinterpret_cast<float4*>(out + (size_t)(m0 + r) * NOUT + n0 + col) = v;
    }
}

// ===================== host launcher =====================
extern "C" void kernel_launch(void* const* d_in, const int* in_sizes, int n_in,
                              void* d_out, int out_size) {
    const float* x  = (const float*)d_in[0];
    const float* bw = (const float*)d_in[1];
    const float* sw = (const float*)d_in[2];
    float* out = (float*)d_out;

    cudaFuncSetAttribute(kan_gemm, cudaFuncAttributeMaxDynamicSharedMemorySize,
                         (int)SMEM_TOTAL);

    kan_prep<<<WPACK_BLOCKS + ACT_BLOCKS, 256>>>(x, bw, sw);
    kan_gemm<<<NCTA, 256, SMEM_TOTAL>>>(out);
    kan_reduce<<<NCTA - 1, 256>>>(out);
}